// round 7
// baseline (speedup 1.0000x reference)
#include <cuda_runtime.h>
#include <cuda_fp16.h>
#include <math.h>

#define NN 50000
#define EE 800000
#define INC 128
#define HIDC 64
#define NHEADS 4
#define NG 64
#define NCLS 10
#define BN_EPS 1e-5f

typedef unsigned int uint;

// ---------------- scratch (static device globals) ---------------------------
__device__ __align__(16) __half g_hh[NN * 256];   // fp16 transformed feats
__device__ __align__(16) float g_agg[NN * 256];   // aggregation output / layer input
__device__ float g_as[NN * NHEADS];
__device__ float g_ad[NN * NHEADS];
__device__ int   g_rp[NN + 1];
__device__ int   g_cur[NN];
__device__ int   g_col[EE];
__device__ float g_bn[2 * 256];
__device__ float g_scl[256];
__device__ float g_sh[256];
__device__ float g_pool[NG * HIDC];
__device__ float g_cnt[NG];

static inline int ceil_div(int a, int b) { return (a + b - 1) / b; }

// ---------------- zero kernels ----------------------------------------------
__global__ void zero_f_k(float* p, int n) {
    int i = blockIdx.x * blockDim.x + threadIdx.x;
    if (i < n) p[i] = 0.f;
}
__global__ void zero_i_k(int* p, int n) {
    int i = blockIdx.x * blockDim.x + threadIdx.x;
    if (i < n) p[i] = 0;
}

// ---------------- CSR build --------------------------------------------------
__global__ void count_k(const int* __restrict__ dst) {
    int e = blockIdx.x * blockDim.x + threadIdx.x;
    if (e < EE) atomicAdd(&g_cur[dst[e]], 1);
}

#define SCAN_T 512
__global__ void scan_k() {
    __shared__ int sh[SCAN_T];
    int t = threadIdx.x;
    int chunk = (NN + SCAN_T - 1) / SCAN_T;
    int base = t * chunk;
    int s = 0;
    for (int j = 0; j < chunk; j++) {
        int idx = base + j;
        if (idx < NN) s += g_cur[idx];
    }
    sh[t] = s;
    __syncthreads();
    for (int off = 1; off < SCAN_T; off <<= 1) {
        int v = (t >= off) ? sh[t - off] : 0;
        __syncthreads();
        sh[t] += v;
        __syncthreads();
    }
    int running = sh[t] - s;
    for (int j = 0; j < chunk; j++) {
        int idx = base + j;
        if (idx < NN) {
            int d = g_cur[idx];
            g_rp[idx] = running;
            g_cur[idx] = running;
            running += d;
        }
    }
    if (t == SCAN_T - 1) g_rp[NN] = sh[SCAN_T - 1];
}

__global__ void fill_k(const int* __restrict__ src, const int* __restrict__ dst) {
    int e = blockIdx.x * blockDim.x + threadIdx.x;
    if (e >= EE) return;
    int p = atomicAdd(&g_cur[dst[e]], 1);
    g_col[p] = src[e];
}

// ---------------- 3xTF32 tensor-core GEMM (smem-resident hi/lo split) -------
#define BM 128
#define BN 64
#define BK 16
#define SAS (BK + 4)   // 20
#define SBS (BN + 8)   // 72

__device__ __forceinline__ uint f2tf32(float x) {
    uint r;
    asm("cvt.rna.tf32.f32 %0, %1;" : "=r"(r) : "f"(x));
    return r;
}
__device__ __forceinline__ void mma8(float* c, const uint* a, const uint* b) {
    asm volatile(
        "mma.sync.aligned.m16n8k8.row.col.f32.tf32.tf32.f32 "
        "{%0,%1,%2,%3}, {%4,%5,%6,%7}, {%8,%9}, {%0,%1,%2,%3};"
        : "+f"(c[0]), "+f"(c[1]), "+f"(c[2]), "+f"(c[3])
        : "r"(a[0]), "r"(a[1]), "r"(a[2]), "r"(a[3]), "r"(b[0]), "r"(b[1]));
}

__global__ void __launch_bounds__(256) tgemm_k(const float* __restrict__ A,
                                               const float* __restrict__ B,
                                               const float* __restrict__ asrc,
                                               const float* __restrict__ adst,
                                               int n, int K, int M, int H,
                                               int useBN) {
    __shared__ uint sAh[BM][SAS];
    __shared__ uint sAl[BM][SAS];
    __shared__ uint sBh[BK][SBS];
    __shared__ uint sBl[BK][SBS];
    __shared__ float sAs[BM];
    __shared__ float sAd[BM];
    int tid = threadIdx.x;
    int lane = tid & 31;
    int wid = tid >> 5;
    int warpM = wid >> 1, warpN = wid & 1;
    int gid = lane >> 2, tq = lane & 3;
    int row0 = blockIdx.x * BM, col0 = blockIdx.y * BN;
    int hd = blockIdx.y;

    int a_r = tid >> 2, a_q4 = (tid & 3) * 4;
    int b_kr = tid >> 4, b_nc4 = (tid & 15) * 4;

    float4 pa[2];
    float4 pb;

    auto loadTiles = [&](int k0) {
        float scl0 = 1.f, scl1 = 1.f, scl2 = 1.f, scl3 = 1.f;
        float sh0 = 0.f, sh1 = 0.f, sh2 = 0.f, sh3 = 0.f;
        if (useBN) {
            scl0 = g_scl[k0 + a_q4 + 0]; sh0 = g_sh[k0 + a_q4 + 0];
            scl1 = g_scl[k0 + a_q4 + 1]; sh1 = g_sh[k0 + a_q4 + 1];
            scl2 = g_scl[k0 + a_q4 + 2]; sh2 = g_sh[k0 + a_q4 + 2];
            scl3 = g_scl[k0 + a_q4 + 3]; sh3 = g_sh[k0 + a_q4 + 3];
        }
#pragma unroll
        for (int i = 0; i < 2; i++) {
            int gr = row0 + i * 64 + a_r;
            float4 v = make_float4(0.f, 0.f, 0.f, 0.f);
            if (gr < n) v = *(const float4*)&A[(size_t)gr * K + k0 + a_q4];
            if (useBN) {
                v.x = v.x * scl0 + sh0;
                v.y = v.y * scl1 + sh1;
                v.z = v.z * scl2 + sh2;
                v.w = v.w * scl3 + sh3;
            }
            pa[i] = v;
        }
        pb = *(const float4*)&B[(size_t)(k0 + b_kr) * M + col0 + b_nc4];
    };
    auto storeTiles = [&]() {
#pragma unroll
        for (int i = 0; i < 2; i++) {
            int r = i * 64 + a_r;
            float vv[4] = {pa[i].x, pa[i].y, pa[i].z, pa[i].w};
            uint hi[4], lo[4];
#pragma unroll
            for (int j = 0; j < 4; j++) {
                hi[j] = f2tf32(vv[j]);
                lo[j] = f2tf32(vv[j] - __uint_as_float(hi[j]));
            }
            *(uint4*)&sAh[r][a_q4] = make_uint4(hi[0], hi[1], hi[2], hi[3]);
            *(uint4*)&sAl[r][a_q4] = make_uint4(lo[0], lo[1], lo[2], lo[3]);
        }
        {
            float vv[4] = {pb.x, pb.y, pb.z, pb.w};
            uint hi[4], lo[4];
#pragma unroll
            for (int j = 0; j < 4; j++) {
                hi[j] = f2tf32(vv[j]);
                lo[j] = f2tf32(vv[j] - __uint_as_float(hi[j]));
            }
            *(uint4*)&sBh[b_kr][b_nc4] = make_uint4(hi[0], hi[1], hi[2], hi[3]);
            *(uint4*)&sBl[b_kr][b_nc4] = make_uint4(lo[0], lo[1], lo[2], lo[3]);
        }
    };

    float c[2][4][4];
#pragma unroll
    for (int mt = 0; mt < 2; mt++)
#pragma unroll
        for (int nt = 0; nt < 4; nt++)
#pragma unroll
            for (int j = 0; j < 4; j++) c[mt][nt][j] = 0.f;

    int nk = K / BK;
    loadTiles(0);
    for (int it = 0; it < nk; it++) {
        storeTiles();
        __syncthreads();
        if (it + 1 < nk) loadTiles((it + 1) * BK);
#pragma unroll
        for (int ks = 0; ks < 2; ks++) {
            int k = ks * 8;
            uint ah[2][4], al[2][4], bh[4][2], bl[4][2];
#pragma unroll
            for (int mt = 0; mt < 2; mt++) {
                int m = warpM * 32 + mt * 16;
                ah[mt][0] = sAh[m + gid][k + tq];
                ah[mt][1] = sAh[m + gid + 8][k + tq];
                ah[mt][2] = sAh[m + gid][k + tq + 4];
                ah[mt][3] = sAh[m + gid + 8][k + tq + 4];
                al[mt][0] = sAl[m + gid][k + tq];
                al[mt][1] = sAl[m + gid + 8][k + tq];
                al[mt][2] = sAl[m + gid][k + tq + 4];
                al[mt][3] = sAl[m + gid + 8][k + tq + 4];
            }
#pragma unroll
            for (int nt = 0; nt < 4; nt++) {
                int nb = warpN * 32 + nt * 8;
                bh[nt][0] = sBh[k + tq][nb + gid];
                bh[nt][1] = sBh[k + tq + 4][nb + gid];
                bl[nt][0] = sBl[k + tq][nb + gid];
                bl[nt][1] = sBl[k + tq + 4][nb + gid];
            }
#pragma unroll
            for (int mt = 0; mt < 2; mt++)
#pragma unroll
                for (int nt = 0; nt < 4; nt++) {
                    mma8(c[mt][nt], ah[mt], bh[nt]);
                    mma8(c[mt][nt], al[mt], bh[nt]);
                    mma8(c[mt][nt], ah[mt], bl[nt]);
                }
        }
        __syncthreads();
    }

    // ---- epilogue: fp16 h store + fused attention logits ----
    if (tid < BM) { sAs[tid] = 0.f; sAd[tid] = 0.f; }
    __syncthreads();

    float pAs[4] = {0.f, 0.f, 0.f, 0.f};
    float pAd[4] = {0.f, 0.f, 0.f, 0.f};
#pragma unroll
    for (int nt = 0; nt < 4; nt++) {
        int cc = warpN * 32 + nt * 8 + tq * 2;
        float a0 = __ldg(&asrc[hd * HIDC + cc]);
        float a1 = __ldg(&asrc[hd * HIDC + cc + 1]);
        float d0 = __ldg(&adst[hd * HIDC + cc]);
        float d1 = __ldg(&adst[hd * HIDC + cc + 1]);
#pragma unroll
        for (int mt = 0; mt < 2; mt++) {
            pAs[mt * 2 + 0] += c[mt][nt][0] * a0 + c[mt][nt][1] * a1;
            pAs[mt * 2 + 1] += c[mt][nt][2] * a0 + c[mt][nt][3] * a1;
            pAd[mt * 2 + 0] += c[mt][nt][0] * d0 + c[mt][nt][1] * d1;
            pAd[mt * 2 + 1] += c[mt][nt][2] * d0 + c[mt][nt][3] * d1;
        }
#pragma unroll
        for (int mt = 0; mt < 2; mt++) {
            int r0g = row0 + warpM * 32 + mt * 16 + gid;
            int r1g = r0g + 8;
            int gc = col0 + cc;
            if (r0g < n)
                *(half2*)&g_hh[(size_t)r0g * M + gc] =
                    __floats2half2_rn(c[mt][nt][0], c[mt][nt][1]);
            if (r1g < n)
                *(half2*)&g_hh[(size_t)r1g * M + gc] =
                    __floats2half2_rn(c[mt][nt][2], c[mt][nt][3]);
        }
    }
#pragma unroll
    for (int j = 0; j < 4; j++) {
        pAs[j] += __shfl_xor_sync(0xffffffffu, pAs[j], 1);
        pAs[j] += __shfl_xor_sync(0xffffffffu, pAs[j], 2);
        pAd[j] += __shfl_xor_sync(0xffffffffu, pAd[j], 1);
        pAd[j] += __shfl_xor_sync(0xffffffffu, pAd[j], 2);
    }
    if (tq == 0) {
#pragma unroll
        for (int mt = 0; mt < 2; mt++)
#pragma unroll
            for (int p = 0; p < 2; p++) {
                int lr = warpM * 32 + mt * 16 + p * 8 + gid;
                atomicAdd(&sAs[lr], pAs[mt * 2 + p]);
                atomicAdd(&sAd[lr], pAd[mt * 2 + p]);
            }
    }
    __syncthreads();
    if (tid < BM) {
        int r = row0 + tid;
        if (r < n) {
            g_as[r * H + hd] = sAs[tid];
            g_ad[r * H + hd] = sAd[tid];
        }
    }
}

// ---------------- gather aggregation, H=4 + fused BN stats ------------------
__global__ void agg4_k(const float* __restrict__ bias) {
    __shared__ float sSum[256];
    __shared__ float sSq[256];
    int tid = threadIdx.x;
    int warp = (blockIdx.x * blockDim.x + tid) >> 5;
    int lane = tid & 31;
    int wInB = tid >> 5;  // 8 warps/block
    // zero stats accumulators
    sSum[tid] = 0.f;
    sSq[tid] = 0.f;
    __syncthreads();
    if (warp < NN) {
        int node = warp;
        int hs = lane >> 3;
        float ad_h = (lane < 4) ? g_ad[node * 4 + lane] : 0.f;
        float den = 0.f;
        float acc[8] = {0.f, 0.f, 0.f, 0.f, 0.f, 0.f, 0.f, 0.f};
        int beg = g_rp[node], end = g_rp[node + 1];
        int j = beg;
        for (; j + 1 < end; j += 2) {
            int s0 = __ldg(&g_col[j]);
            int s1 = __ldg(&g_col[j + 1]);
            float e0 = 0.f, e1 = 0.f;
            if (lane < 4) {
                float v0 = __ldg(&g_as[s0 * 4 + lane]) + ad_h;
                float v1 = __ldg(&g_as[s1 * 4 + lane]) + ad_h;
                v0 = (v0 > 0.f) ? v0 : 0.2f * v0;
                v1 = (v1 > 0.f) ? v1 : 0.2f * v1;
                e0 = __expf(v0);
                e1 = __expf(v1);
                den += e0 + e1;
            }
            uint4 u0 = __ldg((const uint4*)&g_hh[(size_t)s0 * 256 + lane * 8]);
            uint4 u1 = __ldg((const uint4*)&g_hh[(size_t)s1 * 256 + lane * 8]);
            float ex0 = __shfl_sync(0xffffffffu, e0, hs);
            float ex1 = __shfl_sync(0xffffffffu, e1, hs);
            float2 f;
            f = __half22float2(*(half2*)&u0.x); acc[0] += ex0 * f.x; acc[1] += ex0 * f.y;
            f = __half22float2(*(half2*)&u0.y); acc[2] += ex0 * f.x; acc[3] += ex0 * f.y;
            f = __half22float2(*(half2*)&u0.z); acc[4] += ex0 * f.x; acc[5] += ex0 * f.y;
            f = __half22float2(*(half2*)&u0.w); acc[6] += ex0 * f.x; acc[7] += ex0 * f.y;
            f = __half22float2(*(half2*)&u1.x); acc[0] += ex1 * f.x; acc[1] += ex1 * f.y;
            f = __half22float2(*(half2*)&u1.y); acc[2] += ex1 * f.x; acc[3] += ex1 * f.y;
            f = __half22float2(*(half2*)&u1.z); acc[4] += ex1 * f.x; acc[5] += ex1 * f.y;
            f = __half22float2(*(half2*)&u1.w); acc[6] += ex1 * f.x; acc[7] += ex1 * f.y;
        }
        if (j < end) {
            int s0 = __ldg(&g_col[j]);
            float e0 = 0.f;
            if (lane < 4) {
                float v0 = __ldg(&g_as[s0 * 4 + lane]) + ad_h;
                v0 = (v0 > 0.f) ? v0 : 0.2f * v0;
                e0 = __expf(v0);
                den += e0;
            }
            uint4 u0 = __ldg((const uint4*)&g_hh[(size_t)s0 * 256 + lane * 8]);
            float ex0 = __shfl_sync(0xffffffffu, e0, hs);
            float2 f;
            f = __half22float2(*(half2*)&u0.x); acc[0] += ex0 * f.x; acc[1] += ex0 * f.y;
            f = __half22float2(*(half2*)&u0.y); acc[2] += ex0 * f.x; acc[3] += ex0 * f.y;
            f = __half22float2(*(half2*)&u0.z); acc[4] += ex0 * f.x; acc[5] += ex0 * f.y;
            f = __half22float2(*(half2*)&u0.w); acc[6] += ex0 * f.x; acc[7] += ex0 * f.y;
        }
        float denh = __shfl_sync(0xffffffffu, den, hs);
        float inv = (denh > 0.f) ? 1.f / denh : 0.f;
        float4 b0 = __ldg(&((const float4*)bias)[lane * 2]);
        float4 b1 = __ldg(&((const float4*)bias)[lane * 2 + 1]);
        float o[8];
        o[0] = fmaxf(acc[0] * inv + b0.x, 0.f);
        o[1] = fmaxf(acc[1] * inv + b0.y, 0.f);
        o[2] = fmaxf(acc[2] * inv + b0.z, 0.f);
        o[3] = fmaxf(acc[3] * inv + b0.w, 0.f);
        o[4] = fmaxf(acc[4] * inv + b1.x, 0.f);
        o[5] = fmaxf(acc[5] * inv + b1.y, 0.f);
        o[6] = fmaxf(acc[6] * inv + b1.z, 0.f);
        o[7] = fmaxf(acc[7] * inv + b1.w, 0.f);
        float* op = g_agg + (size_t)node * 256 + lane * 8;
        *(float4*)op = make_float4(o[0], o[1], o[2], o[3]);
        *(float4*)(op + 4) = make_float4(o[4], o[5], o[6], o[7]);
        // BN stats partials: channel = lane*8+q; warps collide -> atomic smem
#pragma unroll
        for (int q = 0; q < 8; q++) {
            atomicAdd(&sSum[lane * 8 + q], o[q]);
            atomicAdd(&sSq[lane * 8 + q], o[q] * o[q]);
        }
    }
    __syncthreads();
    // one global atomic per channel per block
    atomicAdd(&g_bn[tid], sSum[tid]);
    atomicAdd(&g_bn[256 + tid], sSq[tid]);
}

// ---------------- gather aggregation, H=1 + fused BN stats ------------------
__global__ void agg1_k(const float* __restrict__ bias) {
    __shared__ float sSum[64];
    __shared__ float sSq[64];
    int tid = threadIdx.x;
    int warp = (blockIdx.x * blockDim.x + tid) >> 5;
    int lane = tid & 31;
    if (tid < 64) { sSum[tid] = 0.f; sSq[tid] = 0.f; }
    __syncthreads();
    if (warp < NN) {
        int node = warp;
        float ad0 = g_ad[node];
        float den = 0.f;
        float accx = 0.f, accy = 0.f;
        int beg = g_rp[node], end = g_rp[node + 1];
        int j = beg;
        for (; j + 1 < end; j += 2) {
            int s0 = __ldg(&g_col[j]);
            int s1 = __ldg(&g_col[j + 1]);
            float e0 = 0.f, e1 = 0.f;
            if (lane == 0) {
                float v0 = __ldg(&g_as[s0]) + ad0;
                float v1 = __ldg(&g_as[s1]) + ad0;
                v0 = (v0 > 0.f) ? v0 : 0.2f * v0;
                v1 = (v1 > 0.f) ? v1 : 0.2f * v1;
                e0 = __expf(v0);
                e1 = __expf(v1);
                den += e0 + e1;
            }
            uint u0 = __ldg((const uint*)&g_hh[(size_t)s0 * 64 + lane * 2]);
            uint u1 = __ldg((const uint*)&g_hh[(size_t)s1 * 64 + lane * 2]);
            e0 = __shfl_sync(0xffffffffu, e0, 0);
            e1 = __shfl_sync(0xffffffffu, e1, 0);
            float2 f0 = __half22float2(*(half2*)&u0);
            float2 f1 = __half22float2(*(half2*)&u1);
            accx += e0 * f0.x + e1 * f1.x;
            accy += e0 * f0.y + e1 * f1.y;
        }
        if (j < end) {
            int s0 = __ldg(&g_col[j]);
            float e0 = 0.f;
            if (lane == 0) {
                float v0 = __ldg(&g_as[s0]) + ad0;
                v0 = (v0 > 0.f) ? v0 : 0.2f * v0;
                e0 = __expf(v0);
                den += e0;
            }
            uint u0 = __ldg((const uint*)&g_hh[(size_t)s0 * 64 + lane * 2]);
            e0 = __shfl_sync(0xffffffffu, e0, 0);
            float2 f0 = __half22float2(*(half2*)&u0);
            accx += e0 * f0.x;
            accy += e0 * f0.y;
        }
        den = __shfl_sync(0xffffffffu, den, 0);
        float inv = (den > 0.f) ? 1.f / den : 0.f;
        float2 b = __ldg(&((const float2*)bias)[lane]);
        float ox = fmaxf(accx * inv + b.x, 0.f);
        float oy = fmaxf(accy * inv + b.y, 0.f);
        *(float2*)(g_agg + (size_t)node * 64 + lane * 2) = make_float2(ox, oy);
        atomicAdd(&sSum[lane * 2], ox);
        atomicAdd(&sSum[lane * 2 + 1], oy);
        atomicAdd(&sSq[lane * 2], ox * ox);
        atomicAdd(&sSq[lane * 2 + 1], oy * oy);
    }
    __syncthreads();
    if (tid < 64) {
        atomicAdd(&g_bn[tid], sSum[tid]);
        atomicAdd(&g_bn[64 + tid], sSq[tid]);
    }
}

__global__ void mkbn_k(const float* __restrict__ gam, const float* __restrict__ bet,
                       int HC, int n) {
    int c = threadIdx.x;
    if (c >= HC) return;
    float inv_n = 1.f / (float)n;
    float mean = g_bn[c] * inv_n;
    float var = g_bn[HC + c] * inv_n - mean * mean;
    float s = rsqrtf(var + BN_EPS) * gam[c];
    g_scl[c] = s;
    g_sh[c] = bet[c] - mean * s;
}

// ---------------- pool (sorted batch; applies final BN inline) ---------------
#define POOL_BLKS 200
__global__ void cnt_k(const int* __restrict__ batch) {
    int n = blockIdx.x * blockDim.x + threadIdx.x;
    if (n < NN) atomicAdd(&g_cnt[batch[n]], 1.f);
}
__global__ void pool2_k(const float* __restrict__ h, const int* __restrict__ batch) {
    int c = threadIdx.x & 63;
    int rl = threadIdx.x >> 6;
    int rowsPer = (NN + POOL_BLKS - 1) / POOL_BLKS;
    int r0 = blockIdx.x * rowsPer;
    int r1 = min(r0 + rowsPer, NN);
    float scl = g_scl[c], shv = g_sh[c];
    float acc = 0.f;
    int curg = -1;
    for (int r = r0 + rl; r < r1; r += 4) {
        int g = __ldg(&batch[r]);
        if (g != curg) {
            if (curg >= 0) atomicAdd(&g_pool[curg * HIDC + c], acc);
            curg = g;
            acc = 0.f;
        }
        acc += h[(size_t)r * HIDC + c] * scl + shv;
    }
    if (curg >= 0) atomicAdd(&g_pool[curg * HIDC + c], acc);
}
__global__ void fc_k(const float* __restrict__ fcW, const float* __restrict__ fcb,
                     float* __restrict__ out) {
    int idx = threadIdx.x;
    if (idx >= NG * NCLS) return;
    int g = idx / NCLS, c = idx - g * NCLS;
    float cnt = fmaxf(g_cnt[g], 1.0f);
    float inv = 1.0f / cnt;
    float s = fcb[c];
#pragma unroll
    for (int k = 0; k < HIDC; k++)
        s += (g_pool[g * HIDC + k] * inv) * fcW[k * NCLS + c];
    out[idx] = s;
}

// ---------------- host orchestration ----------------------------------------
extern "C" void kernel_launch(void* const* d_in, const int* in_sizes, int n_in,
                              void* d_out, int out_size) {
    const float* x   = (const float*)d_in[0];
    const int* ei    = (const int*)d_in[1];
    const int* batch = (const int*)d_in[2];
    const float* W1  = (const float*)d_in[3];
    const float* as1 = (const float*)d_in[4];
    const float* ad1 = (const float*)d_in[5];
    const float* b1  = (const float*)d_in[6];
    const float* g1  = (const float*)d_in[7];
    const float* be1 = (const float*)d_in[8];
    const float* W2  = (const float*)d_in[9];
    const float* as2 = (const float*)d_in[10];
    const float* ad2 = (const float*)d_in[11];
    const float* b2  = (const float*)d_in[12];
    const float* g2  = (const float*)d_in[13];
    const float* be2 = (const float*)d_in[14];
    const float* W3  = (const float*)d_in[15];
    const float* as3 = (const float*)d_in[16];
    const float* ad3 = (const float*)d_in[17];
    const float* b3  = (const float*)d_in[18];
    const float* g3  = (const float*)d_in[19];
    const float* be3 = (const float*)d_in[20];
    const float* fcW = (const float*)d_in[21];
    const float* fcb = (const float*)d_in[22];
    const int* src = ei;
    const int* dst = ei + EE;

    float *bnbuf, *poolbuf, *cntbuf, *aggbuf;
    int* curbuf;
    cudaGetSymbolAddress((void**)&aggbuf, g_agg);
    cudaGetSymbolAddress((void**)&bnbuf, g_bn);
    cudaGetSymbolAddress((void**)&poolbuf, g_pool);
    cudaGetSymbolAddress((void**)&cntbuf, g_cnt);
    cudaGetSymbolAddress((void**)&curbuf, g_cur);

    // ---- build CSR (dst -> list of src) ----
    zero_i_k<<<ceil_div(NN, 256), 256>>>(curbuf, NN);
    count_k<<<ceil_div(EE, 256), 256>>>(dst);
    scan_k<<<1, SCAN_T>>>();
    fill_k<<<ceil_div(EE, 256), 256>>>(src, dst);

    auto run_layer = [&](const float* in, int K, const float* W, const float* asv,
                         const float* adv, const float* b, const float* gam,
                         const float* bet, int H, int useBN) {
        int HC = H * HIDC;
        dim3 gg(ceil_div(NN, BM), HC / BN);
        tgemm_k<<<gg, 256>>>(in, W, asv, adv, NN, K, HC, H, useBN);
        zero_f_k<<<2, 256>>>(bnbuf, 2 * HC);
        if (H == 4)
            agg4_k<<<ceil_div(NN * 32, 256), 256>>>(b);
        else
            agg1_k<<<ceil_div(NN * 32, 256), 256>>>(b);
        mkbn_k<<<1, 256>>>(gam, bet, HC, NN);
    };

    run_layer(x,      INC, W1, as1, ad1, b1, g1, be1, NHEADS, 0);
    run_layer(aggbuf, 256, W2, as2, ad2, b2, g2, be2, NHEADS, 1);
    run_layer(aggbuf, 256, W3, as3, ad3, b3, g3, be3, 1, 1);

    // ---- global mean pool (applies layer-3 BN inline) + FC ----
    zero_f_k<<<ceil_div(NG * HIDC, 256), 256>>>(poolbuf, NG * HIDC);
    zero_f_k<<<1, NG>>>(cntbuf, NG);
    cnt_k<<<ceil_div(NN, 256), 256>>>(batch);
    pool2_k<<<POOL_BLKS, 256>>>(aggbuf, batch);
    fc_k<<<1, 640>>>(fcW, fcb, (float*)d_out);
}

// round 9
// speedup vs baseline: 1.2000x; 1.2000x over previous
#include <cuda_runtime.h>
#include <cuda_fp16.h>
#include <cuda_bf16.h>
#include <math.h>

#define NN 50000
#define EE 800000
#define INC 128
#define HIDC 64
#define NHEADS 4
#define NG 64
#define NCLS 10
#define BN_EPS 1e-5f

typedef unsigned int uint;

// ---------------- scratch (static device globals) ---------------------------
__device__ __align__(16) __half g_hh[NN * 256];   // fp16 transformed feats
__device__ __align__(16) float g_agg[NN * 256];   // aggregation output / layer input
__device__ float g_as[NN * NHEADS];
__device__ float g_ad[NN * NHEADS];
__device__ int   g_rp[NN + 1];
__device__ int   g_cur[NN];
__device__ int   g_col[EE];
__device__ float g_bn[2 * 256];
__device__ float g_scl[256];
__device__ float g_sh[256];
__device__ float g_pool[NG * HIDC];
__device__ float g_cnt[NG];

static inline int ceil_div(int a, int b) { return (a + b - 1) / b; }

// ---------------- zero kernels ----------------------------------------------
__global__ void zero_f_k(float* p, int n) {
    int i = blockIdx.x * blockDim.x + threadIdx.x;
    if (i < n) p[i] = 0.f;
}
__global__ void zero_i_k(int* p, int n) {
    int i = blockIdx.x * blockDim.x + threadIdx.x;
    if (i < n) p[i] = 0;
}

// ---------------- CSR build --------------------------------------------------
__global__ void count_k(const int* __restrict__ dst) {
    int e = blockIdx.x * blockDim.x + threadIdx.x;
    if (e < EE) atomicAdd(&g_cur[dst[e]], 1);
}

#define SCAN_T 512
__global__ void scan_k() {
    __shared__ int sh[SCAN_T];
    int t = threadIdx.x;
    int chunk = (NN + SCAN_T - 1) / SCAN_T;
    int base = t * chunk;
    int s = 0;
    for (int j = 0; j < chunk; j++) {
        int idx = base + j;
        if (idx < NN) s += g_cur[idx];
    }
    sh[t] = s;
    __syncthreads();
    for (int off = 1; off < SCAN_T; off <<= 1) {
        int v = (t >= off) ? sh[t - off] : 0;
        __syncthreads();
        sh[t] += v;
        __syncthreads();
    }
    int running = sh[t] - s;
    for (int j = 0; j < chunk; j++) {
        int idx = base + j;
        if (idx < NN) {
            int d = g_cur[idx];
            g_rp[idx] = running;
            g_cur[idx] = running;
            running += d;
        }
    }
    if (t == SCAN_T - 1) g_rp[NN] = sh[SCAN_T - 1];
}

__global__ void fill_k(const int* __restrict__ src, const int* __restrict__ dst) {
    int e = blockIdx.x * blockDim.x + threadIdx.x;
    if (e >= EE) return;
    int p = atomicAdd(&g_cur[dst[e]], 1);
    g_col[p] = src[e];
}

// ---------------- bf16-split tensor-core GEMM -------------------------------
// a = ah + al (bf16 each); C = ah*bh + al*bh + ah*bl  (error ~2^-16)
#define BM 128
#define BN 64
#define BK 32
#define KP (BK / 2)    // 16 packed bf16x2 columns
#define SAS (KP + 4)   // 20: banks (20g+tq)&31 all distinct
#define SBS (BN + 8)   // 72: banks (8tq+g)&31 all distinct

__device__ __forceinline__ uint pack_bf2(float x, float y) {
    __nv_bfloat162 t = __floats2bfloat162_rn(x, y);
    return *(uint*)&t;
}
__device__ __forceinline__ void mma16(float* c, const uint* a, const uint* b) {
    asm volatile(
        "mma.sync.aligned.m16n8k16.row.col.f32.bf16.bf16.f32 "
        "{%0,%1,%2,%3}, {%4,%5,%6,%7}, {%8,%9}, {%0,%1,%2,%3};"
        : "+f"(c[0]), "+f"(c[1]), "+f"(c[2]), "+f"(c[3])
        : "r"(a[0]), "r"(a[1]), "r"(a[2]), "r"(a[3]), "r"(b[0]), "r"(b[1]));
}

// C = A' @ B; A' = A*scl+sh (folded prev-layer BN). Emits fp16 h + as/ad logits.
__global__ void __launch_bounds__(256) tgemm_k(const float* __restrict__ A,
                                               const float* __restrict__ B,
                                               const float* __restrict__ asrc,
                                               const float* __restrict__ adst,
                                               int n, int K, int M, int H,
                                               int useBN) {
    __shared__ uint sAh[BM][SAS];
    __shared__ uint sAl[BM][SAS];
    __shared__ uint sBh[KP][SBS];
    __shared__ uint sBl[KP][SBS];
    __shared__ float sAs[BM];
    __shared__ float sAd[BM];
    int tid = threadIdx.x;
    int lane = tid & 31;
    int wid = tid >> 5;
    int warpM = wid >> 1, warpN = wid & 1;
    int gid = lane >> 2, tq = lane & 3;
    int row0 = blockIdx.x * BM, col0 = blockIdx.y * BN;
    int hd = blockIdx.y;

    // A: 128x32 floats, 4 float4/thread: rows a_r+32i, k cols a_q4..+3
    int a_r = tid >> 3, a_q4 = (tid & 7) * 4;
    // B: 16 kpairs x 64 n, 4 pairs/thread: n fixed, kpair kp0+4i
    int b_n = tid & 63, b_kp0 = tid >> 6;

    float4 pa[4];
    float2 pbp[4];  // (k even, k odd) for each pair

    auto loadTiles = [&](int k0) {
        float scl0 = 1.f, scl1 = 1.f, scl2 = 1.f, scl3 = 1.f;
        float sh0 = 0.f, sh1 = 0.f, sh2 = 0.f, sh3 = 0.f;
        if (useBN) {
            scl0 = g_scl[k0 + a_q4 + 0]; sh0 = g_sh[k0 + a_q4 + 0];
            scl1 = g_scl[k0 + a_q4 + 1]; sh1 = g_sh[k0 + a_q4 + 1];
            scl2 = g_scl[k0 + a_q4 + 2]; sh2 = g_sh[k0 + a_q4 + 2];
            scl3 = g_scl[k0 + a_q4 + 3]; sh3 = g_sh[k0 + a_q4 + 3];
        }
#pragma unroll
        for (int i = 0; i < 4; i++) {
            int gr = row0 + i * 32 + a_r;
            float4 v = make_float4(0.f, 0.f, 0.f, 0.f);
            if (gr < n) v = *(const float4*)&A[(size_t)gr * K + k0 + a_q4];
            if (useBN) {
                v.x = v.x * scl0 + sh0;
                v.y = v.y * scl1 + sh1;
                v.z = v.z * scl2 + sh2;
                v.w = v.w * scl3 + sh3;
            }
            pa[i] = v;
        }
#pragma unroll
        for (int i = 0; i < 4; i++) {
            int kp = b_kp0 + i * 4;
            pbp[i].x = B[(size_t)(k0 + 2 * kp) * M + col0 + b_n];
            pbp[i].y = B[(size_t)(k0 + 2 * kp + 1) * M + col0 + b_n];
        }
    };
    auto storeTiles = [&]() {
#pragma unroll
        for (int i = 0; i < 4; i++) {
            int r = i * 32 + a_r;
            float vv[4] = {pa[i].x, pa[i].y, pa[i].z, pa[i].w};
            float hi[4], lo[4];
#pragma unroll
            for (int j = 0; j < 4; j++) {
                __nv_bfloat16 bh = __float2bfloat16_rn(vv[j]);
                hi[j] = __bfloat162float(bh);
                lo[j] = vv[j] - hi[j];
            }
            int kp2 = (tid & 7) * 2;
            *(uint2*)&sAh[r][kp2] =
                make_uint2(pack_bf2(hi[0], hi[1]), pack_bf2(hi[2], hi[3]));
            *(uint2*)&sAl[r][kp2] =
                make_uint2(pack_bf2(lo[0], lo[1]), pack_bf2(lo[2], lo[3]));
        }
#pragma unroll
        for (int i = 0; i < 4; i++) {
            int kp = b_kp0 + i * 4;
            float bx = pbp[i].x, by = pbp[i].y;
            __nv_bfloat16 hx = __float2bfloat16_rn(bx);
            __nv_bfloat16 hy = __float2bfloat16_rn(by);
            float fhx = __bfloat162float(hx), fhy = __bfloat162float(hy);
            sBh[kp][b_n] = pack_bf2(fhx, fhy);
            sBl[kp][b_n] = pack_bf2(bx - fhx, by - fhy);
        }
    };

    float c[2][4][4];
#pragma unroll
    for (int mt = 0; mt < 2; mt++)
#pragma unroll
        for (int nt = 0; nt < 4; nt++)
#pragma unroll
            for (int j = 0; j < 4; j++) c[mt][nt][j] = 0.f;

    int nk = K / BK;
    loadTiles(0);
    for (int it = 0; it < nk; it++) {
        storeTiles();
        __syncthreads();
        if (it + 1 < nk) loadTiles((it + 1) * BK);
#pragma unroll
        for (int ks = 0; ks < 2; ks++) {
            int kb = ks * 8;  // kpair base for this k16 step
            uint ah[2][4], al[2][4], bh[4][2], bl[4][2];
#pragma unroll
            for (int mt = 0; mt < 2; mt++) {
                int m = warpM * 32 + mt * 16;
                ah[mt][0] = sAh[m + gid][kb + tq];
                ah[mt][1] = sAh[m + gid + 8][kb + tq];
                ah[mt][2] = sAh[m + gid][kb + tq + 4];
                ah[mt][3] = sAh[m + gid + 8][kb + tq + 4];
                al[mt][0] = sAl[m + gid][kb + tq];
                al[mt][1] = sAl[m + gid + 8][kb + tq];
                al[mt][2] = sAl[m + gid][kb + tq + 4];
                al[mt][3] = sAl[m + gid + 8][kb + tq + 4];
            }
#pragma unroll
            for (int nt = 0; nt < 4; nt++) {
                int nb = warpN * 32 + nt * 8;
                bh[nt][0] = sBh[kb + tq][nb + gid];
                bh[nt][1] = sBh[kb + tq + 4][nb + gid];
                bl[nt][0] = sBl[kb + tq][nb + gid];
                bl[nt][1] = sBl[kb + tq + 4][nb + gid];
            }
#pragma unroll
            for (int mt = 0; mt < 2; mt++)
#pragma unroll
                for (int nt = 0; nt < 4; nt++) {
                    mma16(c[mt][nt], ah[mt], bh[nt]);
                    mma16(c[mt][nt], al[mt], bh[nt]);
                    mma16(c[mt][nt], ah[mt], bl[nt]);
                }
        }
        __syncthreads();
    }

    // ---- epilogue: fp16 h store + fused attention logits ----
    if (tid < BM) { sAs[tid] = 0.f; sAd[tid] = 0.f; }
    __syncthreads();

    float pAs[4] = {0.f, 0.f, 0.f, 0.f};
    float pAd[4] = {0.f, 0.f, 0.f, 0.f};
#pragma unroll
    for (int nt = 0; nt < 4; nt++) {
        int cc = warpN * 32 + nt * 8 + tq * 2;
        float a0 = __ldg(&asrc[hd * HIDC + cc]);
        float a1 = __ldg(&asrc[hd * HIDC + cc + 1]);
        float d0 = __ldg(&adst[hd * HIDC + cc]);
        float d1 = __ldg(&adst[hd * HIDC + cc + 1]);
#pragma unroll
        for (int mt = 0; mt < 2; mt++) {
            pAs[mt * 2 + 0] += c[mt][nt][0] * a0 + c[mt][nt][1] * a1;
            pAs[mt * 2 + 1] += c[mt][nt][2] * a0 + c[mt][nt][3] * a1;
            pAd[mt * 2 + 0] += c[mt][nt][0] * d0 + c[mt][nt][1] * d1;
            pAd[mt * 2 + 1] += c[mt][nt][2] * d0 + c[mt][nt][3] * d1;
        }
#pragma unroll
        for (int mt = 0; mt < 2; mt++) {
            int r0g = row0 + warpM * 32 + mt * 16 + gid;
            int r1g = r0g + 8;
            int gc = col0 + cc;
            if (r0g < n)
                *(half2*)&g_hh[(size_t)r0g * M + gc] =
                    __floats2half2_rn(c[mt][nt][0], c[mt][nt][1]);
            if (r1g < n)
                *(half2*)&g_hh[(size_t)r1g * M + gc] =
                    __floats2half2_rn(c[mt][nt][2], c[mt][nt][3]);
        }
    }
#pragma unroll
    for (int j = 0; j < 4; j++) {
        pAs[j] += __shfl_xor_sync(0xffffffffu, pAs[j], 1);
        pAs[j] += __shfl_xor_sync(0xffffffffu, pAs[j], 2);
        pAd[j] += __shfl_xor_sync(0xffffffffu, pAd[j], 1);
        pAd[j] += __shfl_xor_sync(0xffffffffu, pAd[j], 2);
    }
    if (tq == 0) {
#pragma unroll
        for (int mt = 0; mt < 2; mt++)
#pragma unroll
            for (int p = 0; p < 2; p++) {
                int lr = warpM * 32 + mt * 16 + p * 8 + gid;
                atomicAdd(&sAs[lr], pAs[mt * 2 + p]);
                atomicAdd(&sAd[lr], pAd[mt * 2 + p]);
            }
    }
    __syncthreads();
    if (tid < BM) {
        int r = row0 + tid;
        if (r < n) {
            g_as[r * H + hd] = sAs[tid];
            g_ad[r * H + hd] = sAd[tid];
        }
    }
}

// ---------------- gather aggregation, H=4 + fused BN stats ------------------
__global__ void agg4_k(const float* __restrict__ bias) {
    __shared__ float sSum[256];
    __shared__ float sSq[256];
    int tid = threadIdx.x;
    int warp = (blockIdx.x * blockDim.x + tid) >> 5;
    int lane = tid & 31;
    sSum[tid] = 0.f;
    sSq[tid] = 0.f;
    __syncthreads();
    if (warp < NN) {
        int node = warp;
        int hs = lane >> 3;
        float ad_h = (lane < 4) ? g_ad[node * 4 + lane] : 0.f;
        float den = 0.f;
        float acc[8] = {0.f, 0.f, 0.f, 0.f, 0.f, 0.f, 0.f, 0.f};
        int beg = g_rp[node], end = g_rp[node + 1];
        int j = beg;
        for (; j + 1 < end; j += 2) {
            int s0 = __ldg(&g_col[j]);
            int s1 = __ldg(&g_col[j + 1]);
            float e0 = 0.f, e1 = 0.f;
            if (lane < 4) {
                float v0 = __ldg(&g_as[s0 * 4 + lane]) + ad_h;
                float v1 = __ldg(&g_as[s1 * 4 + lane]) + ad_h;
                v0 = (v0 > 0.f) ? v0 : 0.2f * v0;
                v1 = (v1 > 0.f) ? v1 : 0.2f * v1;
                e0 = __expf(v0);
                e1 = __expf(v1);
                den += e0 + e1;
            }
            uint4 u0 = __ldg((const uint4*)&g_hh[(size_t)s0 * 256 + lane * 8]);
            uint4 u1 = __ldg((const uint4*)&g_hh[(size_t)s1 * 256 + lane * 8]);
            float ex0 = __shfl_sync(0xffffffffu, e0, hs);
            float ex1 = __shfl_sync(0xffffffffu, e1, hs);
            float2 f;
            f = __half22float2(*(half2*)&u0.x); acc[0] += ex0 * f.x; acc[1] += ex0 * f.y;
            f = __half22float2(*(half2*)&u0.y); acc[2] += ex0 * f.x; acc[3] += ex0 * f.y;
            f = __half22float2(*(half2*)&u0.z); acc[4] += ex0 * f.x; acc[5] += ex0 * f.y;
            f = __half22float2(*(half2*)&u0.w); acc[6] += ex0 * f.x; acc[7] += ex0 * f.y;
            f = __half22float2(*(half2*)&u1.x); acc[0] += ex1 * f.x; acc[1] += ex1 * f.y;
            f = __half22float2(*(half2*)&u1.y); acc[2] += ex1 * f.x; acc[3] += ex1 * f.y;
            f = __half22float2(*(half2*)&u1.z); acc[4] += ex1 * f.x; acc[5] += ex1 * f.y;
            f = __half22float2(*(half2*)&u1.w); acc[6] += ex1 * f.x; acc[7] += ex1 * f.y;
        }
        if (j < end) {
            int s0 = __ldg(&g_col[j]);
            float e0 = 0.f;
            if (lane < 4) {
                float v0 = __ldg(&g_as[s0 * 4 + lane]) + ad_h;
                v0 = (v0 > 0.f) ? v0 : 0.2f * v0;
                e0 = __expf(v0);
                den += e0;
            }
            uint4 u0 = __ldg((const uint4*)&g_hh[(size_t)s0 * 256 + lane * 8]);
            float ex0 = __shfl_sync(0xffffffffu, e0, hs);
            float2 f;
            f = __half22float2(*(half2*)&u0.x); acc[0] += ex0 * f.x; acc[1] += ex0 * f.y;
            f = __half22float2(*(half2*)&u0.y); acc[2] += ex0 * f.x; acc[3] += ex0 * f.y;
            f = __half22float2(*(half2*)&u0.z); acc[4] += ex0 * f.x; acc[5] += ex0 * f.y;
            f = __half22float2(*(half2*)&u0.w); acc[6] += ex0 * f.x; acc[7] += ex0 * f.y;
        }
        float denh = __shfl_sync(0xffffffffu, den, hs);
        float inv = (denh > 0.f) ? 1.f / denh : 0.f;
        float4 b0 = __ldg(&((const float4*)bias)[lane * 2]);
        float4 b1 = __ldg(&((const float4*)bias)[lane * 2 + 1]);
        float o[8];
        o[0] = fmaxf(acc[0] * inv + b0.x, 0.f);
        o[1] = fmaxf(acc[1] * inv + b0.y, 0.f);
        o[2] = fmaxf(acc[2] * inv + b0.z, 0.f);
        o[3] = fmaxf(acc[3] * inv + b0.w, 0.f);
        o[4] = fmaxf(acc[4] * inv + b1.x, 0.f);
        o[5] = fmaxf(acc[5] * inv + b1.y, 0.f);
        o[6] = fmaxf(acc[6] * inv + b1.z, 0.f);
        o[7] = fmaxf(acc[7] * inv + b1.w, 0.f);
        float* op = g_agg + (size_t)node * 256 + lane * 8;
        *(float4*)op = make_float4(o[0], o[1], o[2], o[3]);
        *(float4*)(op + 4) = make_float4(o[4], o[5], o[6], o[7]);
#pragma unroll
        for (int q = 0; q < 8; q++) {
            atomicAdd(&sSum[lane * 8 + q], o[q]);
            atomicAdd(&sSq[lane * 8 + q], o[q] * o[q]);
        }
    }
    __syncthreads();
    atomicAdd(&g_bn[tid], sSum[tid]);
    atomicAdd(&g_bn[256 + tid], sSq[tid]);
}

// ---------------- gather aggregation, H=1 + fused BN stats ------------------
__global__ void agg1_k(const float* __restrict__ bias) {
    __shared__ float sSum[64];
    __shared__ float sSq[64];
    int tid = threadIdx.x;
    int warp = (blockIdx.x * blockDim.x + tid) >> 5;
    int lane = tid & 31;
    if (tid < 64) { sSum[tid] = 0.f; sSq[tid] = 0.f; }
    __syncthreads();
    if (warp < NN) {
        int node = warp;
        float ad0 = g_ad[node];
        float den = 0.f;
        float accx = 0.f, accy = 0.f;
        int beg = g_rp[node], end = g_rp[node + 1];
        int j = beg;
        for (; j + 1 < end; j += 2) {
            int s0 = __ldg(&g_col[j]);
            int s1 = __ldg(&g_col[j + 1]);
            float e0 = 0.f, e1 = 0.f;
            if (lane == 0) {
                float v0 = __ldg(&g_as[s0]) + ad0;
                float v1 = __ldg(&g_as[s1]) + ad0;
                v0 = (v0 > 0.f) ? v0 : 0.2f * v0;
                v1 = (v1 > 0.f) ? v1 : 0.2f * v1;
                e0 = __expf(v0);
                e1 = __expf(v1);
                den += e0 + e1;
            }
            uint u0 = __ldg((const uint*)&g_hh[(size_t)s0 * 64 + lane * 2]);
            uint u1 = __ldg((const uint*)&g_hh[(size_t)s1 * 64 + lane * 2]);
            e0 = __shfl_sync(0xffffffffu, e0, 0);
            e1 = __shfl_sync(0xffffffffu, e1, 0);
            float2 f0 = __half22float2(*(half2*)&u0);
            float2 f1 = __half22float2(*(half2*)&u1);
            accx += e0 * f0.x + e1 * f1.x;
            accy += e0 * f0.y + e1 * f1.y;
        }
        if (j < end) {
            int s0 = __ldg(&g_col[j]);
            float e0 = 0.f;
            if (lane == 0) {
                float v0 = __ldg(&g_as[s0]) + ad0;
                v0 = (v0 > 0.f) ? v0 : 0.2f * v0;
                e0 = __expf(v0);
                den += e0;
            }
            uint u0 = __ldg((const uint*)&g_hh[(size_t)s0 * 64 + lane * 2]);
            e0 = __shfl_sync(0xffffffffu, e0, 0);
            float2 f0 = __half22float2(*(half2*)&u0);
            accx += e0 * f0.x;
            accy += e0 * f0.y;
        }
        den = __shfl_sync(0xffffffffu, den, 0);
        float inv = (den > 0.f) ? 1.f / den : 0.f;
        float2 b = __ldg(&((const float2*)bias)[lane]);
        float ox = fmaxf(accx * inv + b.x, 0.f);
        float oy = fmaxf(accy * inv + b.y, 0.f);
        *(float2*)(g_agg + (size_t)node * 64 + lane * 2) = make_float2(ox, oy);
        atomicAdd(&sSum[lane * 2], ox);
        atomicAdd(&sSum[lane * 2 + 1], oy);
        atomicAdd(&sSq[lane * 2], ox * ox);
        atomicAdd(&sSq[lane * 2 + 1], oy * oy);
    }
    __syncthreads();
    if (tid < 64) {
        atomicAdd(&g_bn[tid], sSum[tid]);
        atomicAdd(&g_bn[64 + tid], sSq[tid]);
    }
}

__global__ void mkbn_k(const float* __restrict__ gam, const float* __restrict__ bet,
                       int HC, int n) {
    int c = threadIdx.x;
    if (c >= HC) return;
    float inv_n = 1.f / (float)n;
    float mean = g_bn[c] * inv_n;
    float var = g_bn[HC + c] * inv_n - mean * mean;
    float s = rsqrtf(var + BN_EPS) * gam[c];
    g_scl[c] = s;
    g_sh[c] = bet[c] - mean * s;
}

// ---------------- pool (sorted batch; applies final BN inline) ---------------
#define POOL_BLKS 200
__global__ void cnt_k(const int* __restrict__ batch) {
    int n = blockIdx.x * blockDim.x + threadIdx.x;
    if (n < NN) atomicAdd(&g_cnt[batch[n]], 1.f);
}
__global__ void pool2_k(const float* __restrict__ h, const int* __restrict__ batch) {
    int c = threadIdx.x & 63;
    int rl = threadIdx.x >> 6;
    int rowsPer = (NN + POOL_BLKS - 1) / POOL_BLKS;
    int r0 = blockIdx.x * rowsPer;
    int r1 = min(r0 + rowsPer, NN);
    float scl = g_scl[c], shv = g_sh[c];
    float acc = 0.f;
    int curg = -1;
    for (int r = r0 + rl; r < r1; r += 4) {
        int g = __ldg(&batch[r]);
        if (g != curg) {
            if (curg >= 0) atomicAdd(&g_pool[curg * HIDC + c], acc);
            curg = g;
            acc = 0.f;
        }
        acc += h[(size_t)r * HIDC + c] * scl + shv;
    }
    if (curg >= 0) atomicAdd(&g_pool[curg * HIDC + c], acc);
}
__global__ void fc_k(const float* __restrict__ fcW, const float* __restrict__ fcb,
                     float* __restrict__ out) {
    int idx = threadIdx.x;
    if (idx >= NG * NCLS) return;
    int g = idx / NCLS, c = idx - g * NCLS;
    float cnt = fmaxf(g_cnt[g], 1.0f);
    float inv = 1.0f / cnt;
    float s = fcb[c];
#pragma unroll
    for (int k = 0; k < HIDC; k++)
        s += (g_pool[g * HIDC + k] * inv) * fcW[k * NCLS + c];
    out[idx] = s;
}

// ---------------- host orchestration ----------------------------------------
extern "C" void kernel_launch(void* const* d_in, const int* in_sizes, int n_in,
                              void* d_out, int out_size) {
    const float* x   = (const float*)d_in[0];
    const int* ei    = (const int*)d_in[1];
    const int* batch = (const int*)d_in[2];
    const float* W1  = (const float*)d_in[3];
    const float* as1 = (const float*)d_in[4];
    const float* ad1 = (const float*)d_in[5];
    const float* b1  = (const float*)d_in[6];
    const float* g1  = (const float*)d_in[7];
    const float* be1 = (const float*)d_in[8];
    const float* W2  = (const float*)d_in[9];
    const float* as2 = (const float*)d_in[10];
    const float* ad2 = (const float*)d_in[11];
    const float* b2  = (const float*)d_in[12];
    const float* g2  = (const float*)d_in[13];
    const float* be2 = (const float*)d_in[14];
    const float* W3  = (const float*)d_in[15];
    const float* as3 = (const float*)d_in[16];
    const float* ad3 = (const float*)d_in[17];
    const float* b3  = (const float*)d_in[18];
    const float* g3  = (const float*)d_in[19];
    const float* be3 = (const float*)d_in[20];
    const float* fcW = (const float*)d_in[21];
    const float* fcb = (const float*)d_in[22];
    const int* src = ei;
    const int* dst = ei + EE;

    float *bnbuf, *poolbuf, *cntbuf, *aggbuf;
    int* curbuf;
    cudaGetSymbolAddress((void**)&aggbuf, g_agg);
    cudaGetSymbolAddress((void**)&bnbuf, g_bn);
    cudaGetSymbolAddress((void**)&poolbuf, g_pool);
    cudaGetSymbolAddress((void**)&cntbuf, g_cnt);
    cudaGetSymbolAddress((void**)&curbuf, g_cur);

    // ---- build CSR (dst -> list of src) ----
    zero_i_k<<<ceil_div(NN, 256), 256>>>(curbuf, NN);
    count_k<<<ceil_div(EE, 256), 256>>>(dst);
    scan_k<<<1, SCAN_T>>>();
    fill_k<<<ceil_div(EE, 256), 256>>>(src, dst);

    auto run_layer = [&](const float* in, int K, const float* W, const float* asv,
                         const float* adv, const float* b, const float* gam,
                         const float* bet, int H, int useBN) {
        int HC = H * HIDC;
        dim3 gg(ceil_div(NN, BM), HC / BN);
        tgemm_k<<<gg, 256>>>(in, W, asv, adv, NN, K, HC, H, useBN);
        zero_f_k<<<2, 256>>>(bnbuf, 2 * HC);
        if (H == 4)
            agg4_k<<<ceil_div(NN * 32, 256), 256>>>(b);
        else
            agg1_k<<<ceil_div(NN * 32, 256), 256>>>(b);
        mkbn_k<<<1, 256>>>(gam, bet, HC, NN);
    };

    run_layer(x,      INC, W1, as1, ad1, b1, g1, be1, NHEADS, 0);
    run_layer(aggbuf, 256, W2, as2, ad2, b2, g2, be2, NHEADS, 1);
    run_layer(aggbuf, 256, W3, as3, ad3, b3, g3, be3, 1, 1);

    // ---- global mean pool (applies layer-3 BN inline) + FC ----
    zero_f_k<<<ceil_div(NG * HIDC, 256), 256>>>(poolbuf, NG * HIDC);
    zero_f_k<<<1, NG>>>(cntbuf, NG);
    cnt_k<<<ceil_div(NN, 256), 256>>>(batch);
    pool2_k<<<POOL_BLKS, 256>>>(aggbuf, batch);
    fc_k<<<1, 640>>>(fcW, fcb, (float*)d_out);
}

// round 10
// speedup vs baseline: 1.2574x; 1.0479x over previous
#include <cuda_runtime.h>
#include <cuda_fp16.h>
#include <math.h>

#define NN 50000
#define EE 800000
#define INC 128
#define HIDC 64
#define NHEADS 4
#define NG 64
#define NCLS 10
#define BN_EPS 1e-5f

typedef unsigned int uint;

// ---------------- scratch (static device globals) ---------------------------
__device__ __align__(16) __half g_hh[NN * 256];   // fp16 transformed feats
__device__ __align__(16) float g_agg[NN * 256];   // aggregation output / layer input
__device__ float g_as[NN * NHEADS];
__device__ float g_ad[NN * NHEADS];
__device__ int   g_rp[NN + 1];
__device__ int   g_cur[NN];
__device__ int   g_col[EE];
__device__ float g_bn[2 * 256];
__device__ float g_scl[256];
__device__ float g_sh[256];
__device__ float g_pool[NG * HIDC];
__device__ float g_cnt[NG];

static inline int ceil_div(int a, int b) { return (a + b - 1) / b; }

// ---------------- zero kernels ----------------------------------------------
__global__ void zero_f_k(float* p, int n) {
    int i = blockIdx.x * blockDim.x + threadIdx.x;
    if (i < n) p[i] = 0.f;
}
__global__ void zero_i_k(int* p, int n) {
    int i = blockIdx.x * blockDim.x + threadIdx.x;
    if (i < n) p[i] = 0;
}

// ---------------- CSR build --------------------------------------------------
__global__ void count_k(const int* __restrict__ dst) {
    int e = blockIdx.x * blockDim.x + threadIdx.x;
    if (e < EE) atomicAdd(&g_cur[dst[e]], 1);
}

#define SCAN_T 512
__global__ void scan_k() {
    __shared__ int sh[SCAN_T];
    int t = threadIdx.x;
    int chunk = (NN + SCAN_T - 1) / SCAN_T;
    int base = t * chunk;
    int s = 0;
    for (int j = 0; j < chunk; j++) {
        int idx = base + j;
        if (idx < NN) s += g_cur[idx];
    }
    sh[t] = s;
    __syncthreads();
    for (int off = 1; off < SCAN_T; off <<= 1) {
        int v = (t >= off) ? sh[t - off] : 0;
        __syncthreads();
        sh[t] += v;
        __syncthreads();
    }
    int running = sh[t] - s;
    for (int j = 0; j < chunk; j++) {
        int idx = base + j;
        if (idx < NN) {
            int d = g_cur[idx];
            g_rp[idx] = running;
            g_cur[idx] = running;
            running += d;
        }
    }
    if (t == SCAN_T - 1) g_rp[NN] = sh[SCAN_T - 1];
}

__global__ void fill_k(const int* __restrict__ src, const int* __restrict__ dst) {
    int e = blockIdx.x * blockDim.x + threadIdx.x;
    if (e >= EE) return;
    int p = atomicAdd(&g_cur[dst[e]], 1);
    g_col[p] = src[e];
}

// ---------------- fp16 2-term split tensor-core GEMM ------------------------
// a = ah + al (fp16 each, ~22-bit coverage); b = fp16(b).
// C = ah*bh + al*bh;  error ~ a*(b - bh) ~ 2.4e-4 relative.
#define BM 128
#define BN 64
#define BK 32
#define KP (BK / 2)    // 16 packed fp16x2 columns
#define SAS (KP + 4)   // 20: banks (20g+tq)&31 all distinct
#define SBS (BN + 8)   // 72: banks (8tq+g)&31 all distinct

__device__ __forceinline__ uint pack_h2(float x, float y) {
    __half2 t = __floats2half2_rn(x, y);
    return *(uint*)&t;
}
__device__ __forceinline__ void mma16(float* c, const uint* a, const uint* b) {
    asm volatile(
        "mma.sync.aligned.m16n8k16.row.col.f32.f16.f16.f32 "
        "{%0,%1,%2,%3}, {%4,%5,%6,%7}, {%8,%9}, {%0,%1,%2,%3};"
        : "+f"(c[0]), "+f"(c[1]), "+f"(c[2]), "+f"(c[3])
        : "r"(a[0]), "r"(a[1]), "r"(a[2]), "r"(a[3]), "r"(b[0]), "r"(b[1]));
}

// C = A' @ B; A' = A*scl+sh (folded prev-layer BN). Emits fp16 h + as/ad logits.
__global__ void __launch_bounds__(256) tgemm_k(const float* __restrict__ A,
                                               const float* __restrict__ B,
                                               const float* __restrict__ asrc,
                                               const float* __restrict__ adst,
                                               int n, int K, int M, int H,
                                               int useBN) {
    __shared__ uint sAh[BM][SAS];
    __shared__ uint sAl[BM][SAS];
    __shared__ uint sB[KP][SBS];
    __shared__ float sAs[BM];
    __shared__ float sAd[BM];
    int tid = threadIdx.x;
    int lane = tid & 31;
    int wid = tid >> 5;
    int warpM = wid >> 1, warpN = wid & 1;
    int gid = lane >> 2, tq = lane & 3;
    int row0 = blockIdx.x * BM, col0 = blockIdx.y * BN;
    int hd = blockIdx.y;

    // A: 128x32 floats, 4 float4/thread: rows a_r+32i, k cols a_q4..+3
    int a_r = tid >> 3, a_q4 = (tid & 7) * 4;
    // B: 16 kpairs x 64 n, 4 pairs/thread: n fixed, kpair kp0+4i
    int b_n = tid & 63, b_kp0 = tid >> 6;

    float4 pa[4];
    float2 pbp[4];

    auto loadTiles = [&](int k0) {
        float scl0 = 1.f, scl1 = 1.f, scl2 = 1.f, scl3 = 1.f;
        float sh0 = 0.f, sh1 = 0.f, sh2 = 0.f, sh3 = 0.f;
        if (useBN) {
            scl0 = g_scl[k0 + a_q4 + 0]; sh0 = g_sh[k0 + a_q4 + 0];
            scl1 = g_scl[k0 + a_q4 + 1]; sh1 = g_sh[k0 + a_q4 + 1];
            scl2 = g_scl[k0 + a_q4 + 2]; sh2 = g_sh[k0 + a_q4 + 2];
            scl3 = g_scl[k0 + a_q4 + 3]; sh3 = g_sh[k0 + a_q4 + 3];
        }
#pragma unroll
        for (int i = 0; i < 4; i++) {
            int gr = row0 + i * 32 + a_r;
            float4 v = make_float4(0.f, 0.f, 0.f, 0.f);
            if (gr < n) v = *(const float4*)&A[(size_t)gr * K + k0 + a_q4];
            if (useBN) {
                v.x = v.x * scl0 + sh0;
                v.y = v.y * scl1 + sh1;
                v.z = v.z * scl2 + sh2;
                v.w = v.w * scl3 + sh3;
            }
            pa[i] = v;
        }
#pragma unroll
        for (int i = 0; i < 4; i++) {
            int kp = b_kp0 + i * 4;
            pbp[i].x = B[(size_t)(k0 + 2 * kp) * M + col0 + b_n];
            pbp[i].y = B[(size_t)(k0 + 2 * kp + 1) * M + col0 + b_n];
        }
    };
    auto storeTiles = [&]() {
#pragma unroll
        for (int i = 0; i < 4; i++) {
            int r = i * 32 + a_r;
            float vv[4] = {pa[i].x, pa[i].y, pa[i].z, pa[i].w};
            float hi[4], lo[4];
#pragma unroll
            for (int j = 0; j < 4; j++) {
                __half hh = __float2half_rn(vv[j]);
                hi[j] = __half2float(hh);
                lo[j] = vv[j] - hi[j];
            }
            int kp2 = (tid & 7) * 2;
            *(uint2*)&sAh[r][kp2] =
                make_uint2(pack_h2(hi[0], hi[1]), pack_h2(hi[2], hi[3]));
            *(uint2*)&sAl[r][kp2] =
                make_uint2(pack_h2(lo[0], lo[1]), pack_h2(lo[2], lo[3]));
        }
#pragma unroll
        for (int i = 0; i < 4; i++) {
            int kp = b_kp0 + i * 4;
            sB[kp][b_n] = pack_h2(pbp[i].x, pbp[i].y);
        }
    };

    float c[2][4][4];
#pragma unroll
    for (int mt = 0; mt < 2; mt++)
#pragma unroll
        for (int nt = 0; nt < 4; nt++)
#pragma unroll
            for (int j = 0; j < 4; j++) c[mt][nt][j] = 0.f;

    int nk = K / BK;
    loadTiles(0);
    for (int it = 0; it < nk; it++) {
        storeTiles();
        __syncthreads();
        if (it + 1 < nk) loadTiles((it + 1) * BK);
#pragma unroll
        for (int ks = 0; ks < 2; ks++) {
            int kb = ks * 8;
            uint ah[2][4], al[2][4], bh[4][2];
#pragma unroll
            for (int mt = 0; mt < 2; mt++) {
                int m = warpM * 32 + mt * 16;
                ah[mt][0] = sAh[m + gid][kb + tq];
                ah[mt][1] = sAh[m + gid + 8][kb + tq];
                ah[mt][2] = sAh[m + gid][kb + tq + 4];
                ah[mt][3] = sAh[m + gid + 8][kb + tq + 4];
                al[mt][0] = sAl[m + gid][kb + tq];
                al[mt][1] = sAl[m + gid + 8][kb + tq];
                al[mt][2] = sAl[m + gid][kb + tq + 4];
                al[mt][3] = sAl[m + gid + 8][kb + tq + 4];
            }
#pragma unroll
            for (int nt = 0; nt < 4; nt++) {
                int nb = warpN * 32 + nt * 8;
                bh[nt][0] = sB[kb + tq][nb + gid];
                bh[nt][1] = sB[kb + tq + 4][nb + gid];
            }
#pragma unroll
            for (int mt = 0; mt < 2; mt++)
#pragma unroll
                for (int nt = 0; nt < 4; nt++) {
                    mma16(c[mt][nt], ah[mt], bh[nt]);
                    mma16(c[mt][nt], al[mt], bh[nt]);
                }
        }
        __syncthreads();
    }

    // ---- epilogue: fp16 h store + fused attention logits ----
    if (tid < BM) { sAs[tid] = 0.f; sAd[tid] = 0.f; }
    __syncthreads();

    float pAs[4] = {0.f, 0.f, 0.f, 0.f};
    float pAd[4] = {0.f, 0.f, 0.f, 0.f};
#pragma unroll
    for (int nt = 0; nt < 4; nt++) {
        int cc = warpN * 32 + nt * 8 + tq * 2;
        float a0 = __ldg(&asrc[hd * HIDC + cc]);
        float a1 = __ldg(&asrc[hd * HIDC + cc + 1]);
        float d0 = __ldg(&adst[hd * HIDC + cc]);
        float d1 = __ldg(&adst[hd * HIDC + cc + 1]);
#pragma unroll
        for (int mt = 0; mt < 2; mt++) {
            pAs[mt * 2 + 0] += c[mt][nt][0] * a0 + c[mt][nt][1] * a1;
            pAs[mt * 2 + 1] += c[mt][nt][2] * a0 + c[mt][nt][3] * a1;
            pAd[mt * 2 + 0] += c[mt][nt][0] * d0 + c[mt][nt][1] * d1;
            pAd[mt * 2 + 1] += c[mt][nt][2] * d0 + c[mt][nt][3] * d1;
        }
#pragma unroll
        for (int mt = 0; mt < 2; mt++) {
            int r0g = row0 + warpM * 32 + mt * 16 + gid;
            int r1g = r0g + 8;
            int gc = col0 + cc;
            if (r0g < n)
                *(half2*)&g_hh[(size_t)r0g * M + gc] =
                    __floats2half2_rn(c[mt][nt][0], c[mt][nt][1]);
            if (r1g < n)
                *(half2*)&g_hh[(size_t)r1g * M + gc] =
                    __floats2half2_rn(c[mt][nt][2], c[mt][nt][3]);
        }
    }
#pragma unroll
    for (int j = 0; j < 4; j++) {
        pAs[j] += __shfl_xor_sync(0xffffffffu, pAs[j], 1);
        pAs[j] += __shfl_xor_sync(0xffffffffu, pAs[j], 2);
        pAd[j] += __shfl_xor_sync(0xffffffffu, pAd[j], 1);
        pAd[j] += __shfl_xor_sync(0xffffffffu, pAd[j], 2);
    }
    if (tq == 0) {
#pragma unroll
        for (int mt = 0; mt < 2; mt++)
#pragma unroll
            for (int p = 0; p < 2; p++) {
                int lr = warpM * 32 + mt * 16 + p * 8 + gid;
                atomicAdd(&sAs[lr], pAs[mt * 2 + p]);
                atomicAdd(&sAd[lr], pAd[mt * 2 + p]);
            }
    }
    __syncthreads();
    if (tid < BM) {
        int r = row0 + tid;
        if (r < n) {
            g_as[r * H + hd] = sAs[tid];
            g_ad[r * H + hd] = sAd[tid];
        }
    }
}

// ---------------- gather aggregation, H=4 + fused BN stats ------------------
// unroll x4: front-batched independent loads for MLP against L2 latency
__global__ void agg4_k(const float* __restrict__ bias) {
    __shared__ float sSum[256];
    __shared__ float sSq[256];
    int tid = threadIdx.x;
    int warp = (blockIdx.x * blockDim.x + tid) >> 5;
    int lane = tid & 31;
    sSum[tid] = 0.f;
    sSq[tid] = 0.f;
    __syncthreads();
    if (warp < NN) {
        int node = warp;
        int hs = lane >> 3;
        float ad_h = (lane < 4) ? g_ad[node * 4 + lane] : 0.f;
        float den = 0.f;
        float acc[8] = {0.f, 0.f, 0.f, 0.f, 0.f, 0.f, 0.f, 0.f};
        int beg = g_rp[node], end = g_rp[node + 1];
        int j = beg;
        for (; j + 3 < end; j += 4) {
            int s0 = __ldg(&g_col[j]);
            int s1 = __ldg(&g_col[j + 1]);
            int s2 = __ldg(&g_col[j + 2]);
            int s3 = __ldg(&g_col[j + 3]);
            float e0 = 0.f, e1 = 0.f, e2 = 0.f, e3 = 0.f;
            if (lane < 4) {
                float v0 = __ldg(&g_as[s0 * 4 + lane]) + ad_h;
                float v1 = __ldg(&g_as[s1 * 4 + lane]) + ad_h;
                float v2 = __ldg(&g_as[s2 * 4 + lane]) + ad_h;
                float v3 = __ldg(&g_as[s3 * 4 + lane]) + ad_h;
                v0 = (v0 > 0.f) ? v0 : 0.2f * v0;
                v1 = (v1 > 0.f) ? v1 : 0.2f * v1;
                v2 = (v2 > 0.f) ? v2 : 0.2f * v2;
                v3 = (v3 > 0.f) ? v3 : 0.2f * v3;
                e0 = __expf(v0); e1 = __expf(v1);
                e2 = __expf(v2); e3 = __expf(v3);
                den += (e0 + e1) + (e2 + e3);
            }
            uint4 u0 = __ldg((const uint4*)&g_hh[(size_t)s0 * 256 + lane * 8]);
            uint4 u1 = __ldg((const uint4*)&g_hh[(size_t)s1 * 256 + lane * 8]);
            uint4 u2 = __ldg((const uint4*)&g_hh[(size_t)s2 * 256 + lane * 8]);
            uint4 u3 = __ldg((const uint4*)&g_hh[(size_t)s3 * 256 + lane * 8]);
            float ex0 = __shfl_sync(0xffffffffu, e0, hs);
            float ex1 = __shfl_sync(0xffffffffu, e1, hs);
            float ex2 = __shfl_sync(0xffffffffu, e2, hs);
            float ex3 = __shfl_sync(0xffffffffu, e3, hs);
            float2 f;
            f = __half22float2(*(half2*)&u0.x); acc[0] += ex0 * f.x; acc[1] += ex0 * f.y;
            f = __half22float2(*(half2*)&u0.y); acc[2] += ex0 * f.x; acc[3] += ex0 * f.y;
            f = __half22float2(*(half2*)&u0.z); acc[4] += ex0 * f.x; acc[5] += ex0 * f.y;
            f = __half22float2(*(half2*)&u0.w); acc[6] += ex0 * f.x; acc[7] += ex0 * f.y;
            f = __half22float2(*(half2*)&u1.x); acc[0] += ex1 * f.x; acc[1] += ex1 * f.y;
            f = __half22float2(*(half2*)&u1.y); acc[2] += ex1 * f.x; acc[3] += ex1 * f.y;
            f = __half22float2(*(half2*)&u1.z); acc[4] += ex1 * f.x; acc[5] += ex1 * f.y;
            f = __half22float2(*(half2*)&u1.w); acc[6] += ex1 * f.x; acc[7] += ex1 * f.y;
            f = __half22float2(*(half2*)&u2.x); acc[0] += ex2 * f.x; acc[1] += ex2 * f.y;
            f = __half22float2(*(half2*)&u2.y); acc[2] += ex2 * f.x; acc[3] += ex2 * f.y;
            f = __half22float2(*(half2*)&u2.z); acc[4] += ex2 * f.x; acc[5] += ex2 * f.y;
            f = __half22float2(*(half2*)&u2.w); acc[6] += ex2 * f.x; acc[7] += ex2 * f.y;
            f = __half22float2(*(half2*)&u3.x); acc[0] += ex3 * f.x; acc[1] += ex3 * f.y;
            f = __half22float2(*(half2*)&u3.y); acc[2] += ex3 * f.x; acc[3] += ex3 * f.y;
            f = __half22float2(*(half2*)&u3.z); acc[4] += ex3 * f.x; acc[5] += ex3 * f.y;
            f = __half22float2(*(half2*)&u3.w); acc[6] += ex3 * f.x; acc[7] += ex3 * f.y;
        }
        for (; j < end; j++) {
            int s0 = __ldg(&g_col[j]);
            float e0 = 0.f;
            if (lane < 4) {
                float v0 = __ldg(&g_as[s0 * 4 + lane]) + ad_h;
                v0 = (v0 > 0.f) ? v0 : 0.2f * v0;
                e0 = __expf(v0);
                den += e0;
            }
            uint4 u0 = __ldg((const uint4*)&g_hh[(size_t)s0 * 256 + lane * 8]);
            float ex0 = __shfl_sync(0xffffffffu, e0, hs);
            float2 f;
            f = __half22float2(*(half2*)&u0.x); acc[0] += ex0 * f.x; acc[1] += ex0 * f.y;
            f = __half22float2(*(half2*)&u0.y); acc[2] += ex0 * f.x; acc[3] += ex0 * f.y;
            f = __half22float2(*(half2*)&u0.z); acc[4] += ex0 * f.x; acc[5] += ex0 * f.y;
            f = __half22float2(*(half2*)&u0.w); acc[6] += ex0 * f.x; acc[7] += ex0 * f.y;
        }
        float denh = __shfl_sync(0xffffffffu, den, hs);
        float inv = (denh > 0.f) ? 1.f / denh : 0.f;
        float4 b0 = __ldg(&((const float4*)bias)[lane * 2]);
        float4 b1 = __ldg(&((const float4*)bias)[lane * 2 + 1]);
        float o[8];
        o[0] = fmaxf(acc[0] * inv + b0.x, 0.f);
        o[1] = fmaxf(acc[1] * inv + b0.y, 0.f);
        o[2] = fmaxf(acc[2] * inv + b0.z, 0.f);
        o[3] = fmaxf(acc[3] * inv + b0.w, 0.f);
        o[4] = fmaxf(acc[4] * inv + b1.x, 0.f);
        o[5] = fmaxf(acc[5] * inv + b1.y, 0.f);
        o[6] = fmaxf(acc[6] * inv + b1.z, 0.f);
        o[7] = fmaxf(acc[7] * inv + b1.w, 0.f);
        float* op = g_agg + (size_t)node * 256 + lane * 8;
        *(float4*)op = make_float4(o[0], o[1], o[2], o[3]);
        *(float4*)(op + 4) = make_float4(o[4], o[5], o[6], o[7]);
#pragma unroll
        for (int q = 0; q < 8; q++) {
            atomicAdd(&sSum[lane * 8 + q], o[q]);
            atomicAdd(&sSq[lane * 8 + q], o[q] * o[q]);
        }
    }
    __syncthreads();
    atomicAdd(&g_bn[tid], sSum[tid]);
    atomicAdd(&g_bn[256 + tid], sSq[tid]);
}

// ---------------- gather aggregation, H=1 + fused BN stats ------------------
__global__ void agg1_k(const float* __restrict__ bias) {
    __shared__ float sSum[64];
    __shared__ float sSq[64];
    int tid = threadIdx.x;
    int warp = (blockIdx.x * blockDim.x + tid) >> 5;
    int lane = tid & 31;
    if (tid < 64) { sSum[tid] = 0.f; sSq[tid] = 0.f; }
    __syncthreads();
    if (warp < NN) {
        int node = warp;
        float ad0 = g_ad[node];
        float den = 0.f;
        float accx = 0.f, accy = 0.f;
        int beg = g_rp[node], end = g_rp[node + 1];
        int j = beg;
        for (; j + 3 < end; j += 4) {
            int s0 = __ldg(&g_col[j]);
            int s1 = __ldg(&g_col[j + 1]);
            int s2 = __ldg(&g_col[j + 2]);
            int s3 = __ldg(&g_col[j + 3]);
            float e0 = 0.f, e1 = 0.f, e2 = 0.f, e3 = 0.f;
            if (lane == 0) {
                float v0 = __ldg(&g_as[s0]) + ad0;
                float v1 = __ldg(&g_as[s1]) + ad0;
                float v2 = __ldg(&g_as[s2]) + ad0;
                float v3 = __ldg(&g_as[s3]) + ad0;
                v0 = (v0 > 0.f) ? v0 : 0.2f * v0;
                v1 = (v1 > 0.f) ? v1 : 0.2f * v1;
                v2 = (v2 > 0.f) ? v2 : 0.2f * v2;
                v3 = (v3 > 0.f) ? v3 : 0.2f * v3;
                e0 = __expf(v0); e1 = __expf(v1);
                e2 = __expf(v2); e3 = __expf(v3);
                den += (e0 + e1) + (e2 + e3);
            }
            uint u0 = __ldg((const uint*)&g_hh[(size_t)s0 * 64 + lane * 2]);
            uint u1 = __ldg((const uint*)&g_hh[(size_t)s1 * 64 + lane * 2]);
            uint u2 = __ldg((const uint*)&g_hh[(size_t)s2 * 64 + lane * 2]);
            uint u3 = __ldg((const uint*)&g_hh[(size_t)s3 * 64 + lane * 2]);
            e0 = __shfl_sync(0xffffffffu, e0, 0);
            e1 = __shfl_sync(0xffffffffu, e1, 0);
            e2 = __shfl_sync(0xffffffffu, e2, 0);
            e3 = __shfl_sync(0xffffffffu, e3, 0);
            float2 f0 = __half22float2(*(half2*)&u0);
            float2 f1 = __half22float2(*(half2*)&u1);
            float2 f2 = __half22float2(*(half2*)&u2);
            float2 f3 = __half22float2(*(half2*)&u3);
            accx += (e0 * f0.x + e1 * f1.x) + (e2 * f2.x + e3 * f3.x);
            accy += (e0 * f0.y + e1 * f1.y) + (e2 * f2.y + e3 * f3.y);
        }
        for (; j < end; j++) {
            int s0 = __ldg(&g_col[j]);
            float e0 = 0.f;
            if (lane == 0) {
                float v0 = __ldg(&g_as[s0]) + ad0;
                v0 = (v0 > 0.f) ? v0 : 0.2f * v0;
                e0 = __expf(v0);
                den += e0;
            }
            uint u0 = __ldg((const uint*)&g_hh[(size_t)s0 * 64 + lane * 2]);
            e0 = __shfl_sync(0xffffffffu, e0, 0);
            float2 f0 = __half22float2(*(half2*)&u0);
            accx += e0 * f0.x;
            accy += e0 * f0.y;
        }
        den = __shfl_sync(0xffffffffu, den, 0);
        float inv = (den > 0.f) ? 1.f / den : 0.f;
        float2 b = __ldg(&((const float2*)bias)[lane]);
        float ox = fmaxf(accx * inv + b.x, 0.f);
        float oy = fmaxf(accy * inv + b.y, 0.f);
        *(float2*)(g_agg + (size_t)node * 64 + lane * 2) = make_float2(ox, oy);
        atomicAdd(&sSum[lane * 2], ox);
        atomicAdd(&sSum[lane * 2 + 1], oy);
        atomicAdd(&sSq[lane * 2], ox * ox);
        atomicAdd(&sSq[lane * 2 + 1], oy * oy);
    }
    __syncthreads();
    if (tid < 64) {
        atomicAdd(&g_bn[tid], sSum[tid]);
        atomicAdd(&g_bn[64 + tid], sSq[tid]);
    }
}

__global__ void mkbn_k(const float* __restrict__ gam, const float* __restrict__ bet,
                       int HC, int n) {
    int c = threadIdx.x;
    if (c >= HC) return;
    float inv_n = 1.f / (float)n;
    float mean = g_bn[c] * inv_n;
    float var = g_bn[HC + c] * inv_n - mean * mean;
    float s = rsqrtf(var + BN_EPS) * gam[c];
    g_scl[c] = s;
    g_sh[c] = bet[c] - mean * s;
}

// ---------------- pool (sorted batch; applies final BN inline) ---------------
#define POOL_BLKS 200
__global__ void cnt_k(const int* __restrict__ batch) {
    int n = blockIdx.x * blockDim.x + threadIdx.x;
    if (n < NN) atomicAdd(&g_cnt[batch[n]], 1.f);
}
__global__ void pool2_k(const float* __restrict__ h, const int* __restrict__ batch) {
    int c = threadIdx.x & 63;
    int rl = threadIdx.x >> 6;
    int rowsPer = (NN + POOL_BLKS - 1) / POOL_BLKS;
    int r0 = blockIdx.x * rowsPer;
    int r1 = min(r0 + rowsPer, NN);
    float scl = g_scl[c], shv = g_sh[c];
    float acc = 0.f;
    int curg = -1;
    for (int r = r0 + rl; r < r1; r += 4) {
        int g = __ldg(&batch[r]);
        if (g != curg) {
            if (curg >= 0) atomicAdd(&g_pool[curg * HIDC + c], acc);
            curg = g;
            acc = 0.f;
        }
        acc += h[(size_t)r * HIDC + c] * scl + shv;
    }
    if (curg >= 0) atomicAdd(&g_pool[curg * HIDC + c], acc);
}
__global__ void fc_k(const float* __restrict__ fcW, const float* __restrict__ fcb,
                     float* __restrict__ out) {
    int idx = threadIdx.x;
    if (idx >= NG * NCLS) return;
    int g = idx / NCLS, c = idx - g * NCLS;
    float cnt = fmaxf(g_cnt[g], 1.0f);
    float inv = 1.0f / cnt;
    float s = fcb[c];
#pragma unroll
    for (int k = 0; k < HIDC; k++)
        s += (g_pool[g * HIDC + k] * inv) * fcW[k * NCLS + c];
    out[idx] = s;
}

// ---------------- host orchestration ----------------------------------------
extern "C" void kernel_launch(void* const* d_in, const int* in_sizes, int n_in,
                              void* d_out, int out_size) {
    const float* x   = (const float*)d_in[0];
    const int* ei    = (const int*)d_in[1];
    const int* batch = (const int*)d_in[2];
    const float* W1  = (const float*)d_in[3];
    const float* as1 = (const float*)d_in[4];
    const float* ad1 = (const float*)d_in[5];
    const float* b1  = (const float*)d_in[6];
    const float* g1  = (const float*)d_in[7];
    const float* be1 = (const float*)d_in[8];
    const float* W2  = (const float*)d_in[9];
    const float* as2 = (const float*)d_in[10];
    const float* ad2 = (const float*)d_in[11];
    const float* b2  = (const float*)d_in[12];
    const float* g2  = (const float*)d_in[13];
    const float* be2 = (const float*)d_in[14];
    const float* W3  = (const float*)d_in[15];
    const float* as3 = (const float*)d_in[16];
    const float* ad3 = (const float*)d_in[17];
    const float* b3  = (const float*)d_in[18];
    const float* g3  = (const float*)d_in[19];
    const float* be3 = (const float*)d_in[20];
    const float* fcW = (const float*)d_in[21];
    const float* fcb = (const float*)d_in[22];
    const int* src = ei;
    const int* dst = ei + EE;

    float *bnbuf, *poolbuf, *cntbuf, *aggbuf;
    int* curbuf;
    cudaGetSymbolAddress((void**)&aggbuf, g_agg);
    cudaGetSymbolAddress((void**)&bnbuf, g_bn);
    cudaGetSymbolAddress((void**)&poolbuf, g_pool);
    cudaGetSymbolAddress((void**)&cntbuf, g_cnt);
    cudaGetSymbolAddress((void**)&curbuf, g_cur);

    // ---- build CSR (dst -> list of src) ----
    zero_i_k<<<ceil_div(NN, 256), 256>>>(curbuf, NN);
    count_k<<<ceil_div(EE, 256), 256>>>(dst);
    scan_k<<<1, SCAN_T>>>();
    fill_k<<<ceil_div(EE, 256), 256>>>(src, dst);

    auto run_layer = [&](const float* in, int K, const float* W, const float* asv,
                         const float* adv, const float* b, const float* gam,
                         const float* bet, int H, int useBN) {
        int HC = H * HIDC;
        dim3 gg(ceil_div(NN, BM), HC / BN);
        tgemm_k<<<gg, 256>>>(in, W, asv, adv, NN, K, HC, H, useBN);
        zero_f_k<<<2, 256>>>(bnbuf, 2 * HC);
        if (H == 4)
            agg4_k<<<ceil_div(NN * 32, 256), 256>>>(b);
        else
            agg1_k<<<ceil_div(NN * 32, 256), 256>>>(b);
        mkbn_k<<<1, 256>>>(gam, bet, HC, NN);
    };

    run_layer(x,      INC, W1, as1, ad1, b1, g1, be1, NHEADS, 0);
    run_layer(aggbuf, 256, W2, as2, ad2, b2, g2, be2, NHEADS, 1);
    run_layer(aggbuf, 256, W3, as3, ad3, b3, g3, be3, 1, 1);

    // ---- global mean pool (applies layer-3 BN inline) + FC ----
    zero_f_k<<<ceil_div(NG * HIDC, 256), 256>>>(poolbuf, NG * HIDC);
    zero_f_k<<<1, NG>>>(cntbuf, NG);
    cnt_k<<<ceil_div(NN, 256), 256>>>(batch);
    pool2_k<<<POOL_BLKS, 256>>>(aggbuf, batch);
    fc_k<<<1, 640>>>(fcW, fcb, (float*)d_out);
}

// round 16
// speedup vs baseline: 1.2850x; 1.0219x over previous
#include <cuda_runtime.h>
#include <cuda_fp16.h>
#include <math.h>

#define NN 50000
#define EE 800000
#define INC 128
#define HIDC 64
#define NHEADS 4
#define NG 64
#define NCLS 10
#define BN_EPS 1e-5f

typedef unsigned int uint;

// ---------------- scratch (static device globals) ---------------------------
__device__ __align__(16) __half g_hh[NN * 256];   // fp16 transformed feats
__device__ __align__(16) float g_agg[NN * 256];   // aggregation output / layer input
__device__ float g_as[NN * NHEADS];
__device__ float g_ad[NN * NHEADS];
__device__ int   g_rp[NN + 1];
__device__ int   g_cur[NN];
__device__ int   g_col[EE];
__device__ float g_bn[2 * 256];
__device__ float g_scl[256];
__device__ float g_sh[256];
__device__ float g_pool[NG * HIDC];
__device__ float g_cnt[NG];

static inline int ceil_div(int a, int b) { return (a + b - 1) / b; }

// ---------------- zero kernels ----------------------------------------------
__global__ void zero_f_k(float* p, int n) {
    int i = blockIdx.x * blockDim.x + threadIdx.x;
    if (i < n) p[i] = 0.f;
}
__global__ void zero_i_k(int* p, int n) {
    int i = blockIdx.x * blockDim.x + threadIdx.x;
    if (i < n) p[i] = 0;
}

// ---------------- CSR build --------------------------------------------------
__global__ void count_k(const int* __restrict__ dst) {
    int e = blockIdx.x * blockDim.x + threadIdx.x;
    if (e < EE) atomicAdd(&g_cur[dst[e]], 1);
}

#define SCAN_T 512
__global__ void scan_k() {
    __shared__ int sh[SCAN_T];
    int t = threadIdx.x;
    int chunk = (NN + SCAN_T - 1) / SCAN_T;
    int base = t * chunk;
    int s = 0;
    for (int j = 0; j < chunk; j++) {
        int idx = base + j;
        if (idx < NN) s += g_cur[idx];
    }
    sh[t] = s;
    __syncthreads();
    for (int off = 1; off < SCAN_T; off <<= 1) {
        int v = (t >= off) ? sh[t - off] : 0;
        __syncthreads();
        sh[t] += v;
        __syncthreads();
    }
    int running = sh[t] - s;
    for (int j = 0; j < chunk; j++) {
        int idx = base + j;
        if (idx < NN) {
            int d = g_cur[idx];
            g_rp[idx] = running;
            g_cur[idx] = running;
            running += d;
        }
    }
    if (t == SCAN_T - 1) g_rp[NN] = sh[SCAN_T - 1];
}

__global__ void fill_k(const int* __restrict__ src, const int* __restrict__ dst) {
    int e = blockIdx.x * blockDim.x + threadIdx.x;
    if (e >= EE) return;
    int p = atomicAdd(&g_cur[dst[e]], 1);
    g_col[p] = src[e];
}

// ---------------- fp16 3-term split GEMM with ldmatrix ----------------------
// a = ah + al (fp16); b = bh + bl (fp16).
// C = ah*bh + al*bh + ah*bl   (drops al*bl ~ 1e-7; total GEMM err ~1e-6)
#define BM 128
#define BN 64
#define BK 32
#define SA_H 40        // A row stride in halves (80B): ldmatrix conflict-free
#define SB_U 36        // B row stride in uints (144B): ldmatrix conflict-free

__device__ __forceinline__ uint pack2h(__half x, __half y) {
    __half2 t = __halves2half2(x, y);
    return *(uint*)&t;
}
__device__ __forceinline__ void mma16(float* c, const uint* a, const uint* b) {
    asm volatile(
        "mma.sync.aligned.m16n8k16.row.col.f32.f16.f16.f32 "
        "{%0,%1,%2,%3}, {%4,%5,%6,%7}, {%8,%9}, {%0,%1,%2,%3};"
        : "+f"(c[0]), "+f"(c[1]), "+f"(c[2]), "+f"(c[3])
        : "r"(a[0]), "r"(a[1]), "r"(a[2]), "r"(a[3]), "r"(b[0]), "r"(b[1]));
}
__device__ __forceinline__ void ldsm4(uint& r0, uint& r1, uint& r2, uint& r3, uint addr) {
    asm volatile("ldmatrix.sync.aligned.m8n8.x4.shared.b16 {%0,%1,%2,%3}, [%4];"
                 : "=r"(r0), "=r"(r1), "=r"(r2), "=r"(r3) : "r"(addr));
}
__device__ __forceinline__ void ldsm4t(uint& r0, uint& r1, uint& r2, uint& r3, uint addr) {
    asm volatile("ldmatrix.sync.aligned.m8n8.x4.trans.shared.b16 {%0,%1,%2,%3}, [%4];"
                 : "=r"(r0), "=r"(r1), "=r"(r2), "=r"(r3) : "r"(addr));
}

// C = A' @ B; A' = A*scl+sh (folded prev-layer BN). Emits fp16 h + as/ad logits.
__global__ void __launch_bounds__(256) tgemm_k(const float* __restrict__ A,
                                               const float* __restrict__ B,
                                               const float* __restrict__ asrc,
                                               const float* __restrict__ adst,
                                               int n, int K, int M, int H,
                                               int useBN) {
    __shared__ __align__(16) __half sAh[BM][SA_H];
    __shared__ __align__(16) __half sAl[BM][SA_H];
    __shared__ __align__(16) uint sBh[BK][SB_U];
    __shared__ __align__(16) uint sBl[BK][SB_U];
    __shared__ float sAs[BM];
    __shared__ float sAd[BM];
    int tid = threadIdx.x;
    int lane = tid & 31;
    int wid = tid >> 5;
    int warpM = wid >> 1, warpN = wid & 1;
    int gid = lane >> 2, tq = lane & 3;
    int row0 = blockIdx.x * BM, col0 = blockIdx.y * BN;
    int hd = blockIdx.y;

    // A loader: rows a_r + 32i, k cols a_q4..+3 (floats)
    int a_r = tid >> 3, a_q4 = (tid & 7) * 4;
    // B loader: n pair b_n2 (n=2*b_n2), k rows b_k + 8i
    int b_n2 = tid & 31, b_k = tid >> 5;

    float4 pa[4];
    float2 pbv[4];

    auto loadTiles = [&](int k0) {
        float scl0 = 1.f, scl1 = 1.f, scl2 = 1.f, scl3 = 1.f;
        float sh0 = 0.f, sh1 = 0.f, sh2 = 0.f, sh3 = 0.f;
        if (useBN) {
            scl0 = g_scl[k0 + a_q4 + 0]; sh0 = g_sh[k0 + a_q4 + 0];
            scl1 = g_scl[k0 + a_q4 + 1]; sh1 = g_sh[k0 + a_q4 + 1];
            scl2 = g_scl[k0 + a_q4 + 2]; sh2 = g_sh[k0 + a_q4 + 2];
            scl3 = g_scl[k0 + a_q4 + 3]; sh3 = g_sh[k0 + a_q4 + 3];
        }
#pragma unroll
        for (int i = 0; i < 4; i++) {
            int gr = row0 + i * 32 + a_r;
            float4 v = make_float4(0.f, 0.f, 0.f, 0.f);
            if (gr < n) v = *(const float4*)&A[(size_t)gr * K + k0 + a_q4];
            if (useBN) {
                v.x = v.x * scl0 + sh0;
                v.y = v.y * scl1 + sh1;
                v.z = v.z * scl2 + sh2;
                v.w = v.w * scl3 + sh3;
            }
            pa[i] = v;
        }
#pragma unroll
        for (int i = 0; i < 4; i++) {
            int k = b_k + i * 8;
            pbv[i] = *(const float2*)&B[(size_t)(k0 + k) * M + col0 + 2 * b_n2];
        }
    };
    auto storeTiles = [&]() {
#pragma unroll
        for (int i = 0; i < 4; i++) {
            int r = i * 32 + a_r;
            float vv[4] = {pa[i].x, pa[i].y, pa[i].z, pa[i].w};
            __half hh[4], hl[4];
#pragma unroll
            for (int j = 0; j < 4; j++) {
                hh[j] = __float2half_rn(vv[j]);
                hl[j] = __float2half_rn(vv[j] - __half2float(hh[j]));
            }
            *(uint2*)&sAh[r][a_q4] = make_uint2(pack2h(hh[0], hh[1]), pack2h(hh[2], hh[3]));
            *(uint2*)&sAl[r][a_q4] = make_uint2(pack2h(hl[0], hl[1]), pack2h(hl[2], hl[3]));
        }
#pragma unroll
        for (int i = 0; i < 4; i++) {
            int k = b_k + i * 8;
            __half hx = __float2half_rn(pbv[i].x);
            __half hy = __float2half_rn(pbv[i].y);
            __half lx = __float2half_rn(pbv[i].x - __half2float(hx));
            __half ly = __float2half_rn(pbv[i].y - __half2float(hy));
            sBh[k][b_n2] = pack2h(hx, hy);
            sBl[k][b_n2] = pack2h(lx, ly);
        }
    };

    float c[2][4][4];
#pragma unroll
    for (int mt = 0; mt < 2; mt++)
#pragma unroll
        for (int nt = 0; nt < 4; nt++)
#pragma unroll
            for (int j = 0; j < 4; j++) c[mt][nt][j] = 0.f;

    uint baseAh = (uint)__cvta_generic_to_shared(&sAh[0][0]);
    uint baseAl = (uint)__cvta_generic_to_shared(&sAl[0][0]);
    uint baseBh = (uint)__cvta_generic_to_shared(&sBh[0][0]);
    uint baseBl = (uint)__cvta_generic_to_shared(&sBl[0][0]);
    int r8 = lane & 7, q = lane >> 3;
    // A ldmatrix row/col (per quadrant): row = m + (q&1)*8 + r8; kcol = (q>>1)*8
    int aRowOff = ((q & 1) << 3) + r8;
    int aColOff = (q >> 1) << 3;
    // B ldmatrix: row = k + r8; ucol = warpN*16 + q*4
    int bUcol = warpN * 16 + q * 4;

    int nk = K / BK;
    loadTiles(0);
    for (int it = 0; it < nk; it++) {
        storeTiles();
        __syncthreads();
        if (it + 1 < nk) loadTiles((it + 1) * BK);
#pragma unroll
        for (int ks = 0; ks < 2; ks++) {
            uint ah[2][4], al[2][4], bh[4][2], bl[4][2];
#pragma unroll
            for (int mt = 0; mt < 2; mt++) {
                int m = warpM * 32 + mt * 16 + aRowOff;
                uint aoff = (uint)(m * (SA_H * 2) + (ks * 16 + aColOff) * 2);
                ldsm4(ah[mt][0], ah[mt][1], ah[mt][2], ah[mt][3], baseAh + aoff);
                ldsm4(al[mt][0], al[mt][1], al[mt][2], al[mt][3], baseAl + aoff);
            }
            {
                uint off0 = (uint)(((ks * 16 + r8) * SB_U + bUcol) * 4);
                uint off1 = (uint)(((ks * 16 + 8 + r8) * SB_U + bUcol) * 4);
                ldsm4t(bh[0][0], bh[1][0], bh[2][0], bh[3][0], baseBh + off0);
                ldsm4t(bh[0][1], bh[1][1], bh[2][1], bh[3][1], baseBh + off1);
                ldsm4t(bl[0][0], bl[1][0], bl[2][0], bl[3][0], baseBl + off0);
                ldsm4t(bl[0][1], bl[1][1], bl[2][1], bl[3][1], baseBl + off1);
            }
#pragma unroll
            for (int mt = 0; mt < 2; mt++)
#pragma unroll
                for (int nt = 0; nt < 4; nt++) {
                    mma16(c[mt][nt], ah[mt], bh[nt]);
                    mma16(c[mt][nt], al[mt], bh[nt]);
                    mma16(c[mt][nt], ah[mt], bl[nt]);
                }
        }
        __syncthreads();
    }

    // ---- epilogue: fp16 h store + fused attention logits ----
    if (tid < BM) { sAs[tid] = 0.f; sAd[tid] = 0.f; }
    __syncthreads();

    float pAs[4] = {0.f, 0.f, 0.f, 0.f};
    float pAd[4] = {0.f, 0.f, 0.f, 0.f};
#pragma unroll
    for (int nt = 0; nt < 4; nt++) {
        int cc = warpN * 32 + nt * 8 + tq * 2;
        float a0 = __ldg(&asrc[hd * HIDC + cc]);
        float a1 = __ldg(&asrc[hd * HIDC + cc + 1]);
        float d0 = __ldg(&adst[hd * HIDC + cc]);
        float d1 = __ldg(&adst[hd * HIDC + cc + 1]);
#pragma unroll
        for (int mt = 0; mt < 2; mt++) {
            pAs[mt * 2 + 0] += c[mt][nt][0] * a0 + c[mt][nt][1] * a1;
            pAs[mt * 2 + 1] += c[mt][nt][2] * a0 + c[mt][nt][3] * a1;
            pAd[mt * 2 + 0] += c[mt][nt][0] * d0 + c[mt][nt][1] * d1;
            pAd[mt * 2 + 1] += c[mt][nt][2] * d0 + c[mt][nt][3] * d1;
        }
#pragma unroll
        for (int mt = 0; mt < 2; mt++) {
            int r0g = row0 + warpM * 32 + mt * 16 + gid;
            int r1g = r0g + 8;
            int gc = col0 + cc;
            if (r0g < n)
                *(half2*)&g_hh[(size_t)r0g * M + gc] =
                    __floats2half2_rn(c[mt][nt][0], c[mt][nt][1]);
            if (r1g < n)
                *(half2*)&g_hh[(size_t)r1g * M + gc] =
                    __floats2half2_rn(c[mt][nt][2], c[mt][nt][3]);
        }
    }
#pragma unroll
    for (int j = 0; j < 4; j++) {
        pAs[j] += __shfl_xor_sync(0xffffffffu, pAs[j], 1);
        pAs[j] += __shfl_xor_sync(0xffffffffu, pAs[j], 2);
        pAd[j] += __shfl_xor_sync(0xffffffffu, pAd[j], 1);
        pAd[j] += __shfl_xor_sync(0xffffffffu, pAd[j], 2);
    }
    if (tq == 0) {
#pragma unroll
        for (int mt = 0; mt < 2; mt++)
#pragma unroll
            for (int p = 0; p < 2; p++) {
                int lr = warpM * 32 + mt * 16 + p * 8 + gid;
                atomicAdd(&sAs[lr], pAs[mt * 2 + p]);
                atomicAdd(&sAd[lr], pAd[mt * 2 + p]);
            }
    }
    __syncthreads();
    if (tid < BM) {
        int r = row0 + tid;
        if (r < n) {
            g_as[r * H + hd] = sAs[tid];
            g_ad[r * H + hd] = sAd[tid];
        }
    }
}

// ---------------- gather aggregation, H=4 + fused BN stats ------------------
__global__ void agg4_k(const float* __restrict__ bias) {
    __shared__ float sSum[256];
    __shared__ float sSq[256];
    int tid = threadIdx.x;
    int warp = (blockIdx.x * blockDim.x + tid) >> 5;
    int lane = tid & 31;
    sSum[tid] = 0.f;
    sSq[tid] = 0.f;
    __syncthreads();
    if (warp < NN) {
        int node = warp;
        int hs = lane >> 3;
        float ad_h = (lane < 4) ? g_ad[node * 4 + lane] : 0.f;
        float den = 0.f;
        float acc[8] = {0.f, 0.f, 0.f, 0.f, 0.f, 0.f, 0.f, 0.f};
        int beg = g_rp[node], end = g_rp[node + 1];
        int j = beg;
        for (; j + 3 < end; j += 4) {
            int s0 = __ldg(&g_col[j]);
            int s1 = __ldg(&g_col[j + 1]);
            int s2 = __ldg(&g_col[j + 2]);
            int s3 = __ldg(&g_col[j + 3]);
            float e0 = 0.f, e1 = 0.f, e2 = 0.f, e3 = 0.f;
            if (lane < 4) {
                float v0 = __ldg(&g_as[s0 * 4 + lane]) + ad_h;
                float v1 = __ldg(&g_as[s1 * 4 + lane]) + ad_h;
                float v2 = __ldg(&g_as[s2 * 4 + lane]) + ad_h;
                float v3 = __ldg(&g_as[s3 * 4 + lane]) + ad_h;
                v0 = (v0 > 0.f) ? v0 : 0.2f * v0;
                v1 = (v1 > 0.f) ? v1 : 0.2f * v1;
                v2 = (v2 > 0.f) ? v2 : 0.2f * v2;
                v3 = (v3 > 0.f) ? v3 : 0.2f * v3;
                e0 = __expf(v0); e1 = __expf(v1);
                e2 = __expf(v2); e3 = __expf(v3);
                den += (e0 + e1) + (e2 + e3);
            }
            uint4 u0 = __ldg((const uint4*)&g_hh[(size_t)s0 * 256 + lane * 8]);
            uint4 u1 = __ldg((const uint4*)&g_hh[(size_t)s1 * 256 + lane * 8]);
            uint4 u2 = __ldg((const uint4*)&g_hh[(size_t)s2 * 256 + lane * 8]);
            uint4 u3 = __ldg((const uint4*)&g_hh[(size_t)s3 * 256 + lane * 8]);
            float ex0 = __shfl_sync(0xffffffffu, e0, hs);
            float ex1 = __shfl_sync(0xffffffffu, e1, hs);
            float ex2 = __shfl_sync(0xffffffffu, e2, hs);
            float ex3 = __shfl_sync(0xffffffffu, e3, hs);
            float2 f;
            f = __half22float2(*(half2*)&u0.x); acc[0] += ex0 * f.x; acc[1] += ex0 * f.y;
            f = __half22float2(*(half2*)&u0.y); acc[2] += ex0 * f.x; acc[3] += ex0 * f.y;
            f = __half22float2(*(half2*)&u0.z); acc[4] += ex0 * f.x; acc[5] += ex0 * f.y;
            f = __half22float2(*(half2*)&u0.w); acc[6] += ex0 * f.x; acc[7] += ex0 * f.y;
            f = __half22float2(*(half2*)&u1.x); acc[0] += ex1 * f.x; acc[1] += ex1 * f.y;
            f = __half22float2(*(half2*)&u1.y); acc[2] += ex1 * f.x; acc[3] += ex1 * f.y;
            f = __half22float2(*(half2*)&u1.z); acc[4] += ex1 * f.x; acc[5] += ex1 * f.y;
            f = __half22float2(*(half2*)&u1.w); acc[6] += ex1 * f.x; acc[7] += ex1 * f.y;
            f = __half22float2(*(half2*)&u2.x); acc[0] += ex2 * f.x; acc[1] += ex2 * f.y;
            f = __half22float2(*(half2*)&u2.y); acc[2] += ex2 * f.x; acc[3] += ex2 * f.y;
            f = __half22float2(*(half2*)&u2.z); acc[4] += ex2 * f.x; acc[5] += ex2 * f.y;
            f = __half22float2(*(half2*)&u2.w); acc[6] += ex2 * f.x; acc[7] += ex2 * f.y;
            f = __half22float2(*(half2*)&u3.x); acc[0] += ex3 * f.x; acc[1] += ex3 * f.y;
            f = __half22float2(*(half2*)&u3.y); acc[2] += ex3 * f.x; acc[3] += ex3 * f.y;
            f = __half22float2(*(half2*)&u3.z); acc[4] += ex3 * f.x; acc[5] += ex3 * f.y;
            f = __half22float2(*(half2*)&u3.w); acc[6] += ex3 * f.x; acc[7] += ex3 * f.y;
        }
        for (; j < end; j++) {
            int s0 = __ldg(&g_col[j]);
            float e0 = 0.f;
            if (lane < 4) {
                float v0 = __ldg(&g_as[s0 * 4 + lane]) + ad_h;
                v0 = (v0 > 0.f) ? v0 : 0.2f * v0;
                e0 = __expf(v0);
                den += e0;
            }
            uint4 u0 = __ldg((const uint4*)&g_hh[(size_t)s0 * 256 + lane * 8]);
            float ex0 = __shfl_sync(0xffffffffu, e0, hs);
            float2 f;
            f = __half22float2(*(half2*)&u0.x); acc[0] += ex0 * f.x; acc[1] += ex0 * f.y;
            f = __half22float2(*(half2*)&u0.y); acc[2] += ex0 * f.x; acc[3] += ex0 * f.y;
            f = __half22float2(*(half2*)&u0.z); acc[4] += ex0 * f.x; acc[5] += ex0 * f.y;
            f = __half22float2(*(half2*)&u0.w); acc[6] += ex0 * f.x; acc[7] += ex0 * f.y;
        }
        float denh = __shfl_sync(0xffffffffu, den, hs);
        float inv = (denh > 0.f) ? 1.f / denh : 0.f;
        float4 b0 = __ldg(&((const float4*)bias)[lane * 2]);
        float4 b1 = __ldg(&((const float4*)bias)[lane * 2 + 1]);
        float o[8];
        o[0] = fmaxf(acc[0] * inv + b0.x, 0.f);
        o[1] = fmaxf(acc[1] * inv + b0.y, 0.f);
        o[2] = fmaxf(acc[2] * inv + b0.z, 0.f);
        o[3] = fmaxf(acc[3] * inv + b0.w, 0.f);
        o[4] = fmaxf(acc[4] * inv + b1.x, 0.f);
        o[5] = fmaxf(acc[5] * inv + b1.y, 0.f);
        o[6] = fmaxf(acc[6] * inv + b1.z, 0.f);
        o[7] = fmaxf(acc[7] * inv + b1.w, 0.f);
        float* op = g_agg + (size_t)node * 256 + lane * 8;
        *(float4*)op = make_float4(o[0], o[1], o[2], o[3]);
        *(float4*)(op + 4) = make_float4(o[4], o[5], o[6], o[7]);
#pragma unroll
        for (int q = 0; q < 8; q++) {
            atomicAdd(&sSum[lane * 8 + q], o[q]);
            atomicAdd(&sSq[lane * 8 + q], o[q] * o[q]);
        }
    }
    __syncthreads();
    atomicAdd(&g_bn[tid], sSum[tid]);
    atomicAdd(&g_bn[256 + tid], sSq[tid]);
}

// ---------------- gather aggregation, H=1 + fused BN stats ------------------
__global__ void agg1_k(const float* __restrict__ bias) {
    __shared__ float sSum[64];
    __shared__ float sSq[64];
    int tid = threadIdx.x;
    int warp = (blockIdx.x * blockDim.x + tid) >> 5;
    int lane = tid & 31;
    if (tid < 64) { sSum[tid] = 0.f; sSq[tid] = 0.f; }
    __syncthreads();
    if (warp < NN) {
        int node = warp;
        float ad0 = g_ad[node];
        float den = 0.f;
        float accx = 0.f, accy = 0.f;
        int beg = g_rp[node], end = g_rp[node + 1];
        int j = beg;
        for (; j + 3 < end; j += 4) {
            int s0 = __ldg(&g_col[j]);
            int s1 = __ldg(&g_col[j + 1]);
            int s2 = __ldg(&g_col[j + 2]);
            int s3 = __ldg(&g_col[j + 3]);
            float e0 = 0.f, e1 = 0.f, e2 = 0.f, e3 = 0.f;
            if (lane == 0) {
                float v0 = __ldg(&g_as[s0]) + ad0;
                float v1 = __ldg(&g_as[s1]) + ad0;
                float v2 = __ldg(&g_as[s2]) + ad0;
                float v3 = __ldg(&g_as[s3]) + ad0;
                v0 = (v0 > 0.f) ? v0 : 0.2f * v0;
                v1 = (v1 > 0.f) ? v1 : 0.2f * v1;
                v2 = (v2 > 0.f) ? v2 : 0.2f * v2;
                v3 = (v3 > 0.f) ? v3 : 0.2f * v3;
                e0 = __expf(v0); e1 = __expf(v1);
                e2 = __expf(v2); e3 = __expf(v3);
                den += (e0 + e1) + (e2 + e3);
            }
            uint u0 = __ldg((const uint*)&g_hh[(size_t)s0 * 64 + lane * 2]);
            uint u1 = __ldg((const uint*)&g_hh[(size_t)s1 * 64 + lane * 2]);
            uint u2 = __ldg((const uint*)&g_hh[(size_t)s2 * 64 + lane * 2]);
            uint u3 = __ldg((const uint*)&g_hh[(size_t)s3 * 64 + lane * 2]);
            e0 = __shfl_sync(0xffffffffu, e0, 0);
            e1 = __shfl_sync(0xffffffffu, e1, 0);
            e2 = __shfl_sync(0xffffffffu, e2, 0);
            e3 = __shfl_sync(0xffffffffu, e3, 0);
            float2 f0 = __half22float2(*(half2*)&u0);
            float2 f1 = __half22float2(*(half2*)&u1);
            float2 f2 = __half22float2(*(half2*)&u2);
            float2 f3 = __half22float2(*(half2*)&u3);
            accx += (e0 * f0.x + e1 * f1.x) + (e2 * f2.x + e3 * f3.x);
            accy += (e0 * f0.y + e1 * f1.y) + (e2 * f2.y + e3 * f3.y);
        }
        for (; j < end; j++) {
            int s0 = __ldg(&g_col[j]);
            float e0 = 0.f;
            if (lane == 0) {
                float v0 = __ldg(&g_as[s0]) + ad0;
                v0 = (v0 > 0.f) ? v0 : 0.2f * v0;
                e0 = __expf(v0);
                den += e0;
            }
            uint u0 = __ldg((const uint*)&g_hh[(size_t)s0 * 64 + lane * 2]);
            e0 = __shfl_sync(0xffffffffu, e0, 0);
            float2 f0 = __half22float2(*(half2*)&u0);
            accx += e0 * f0.x;
            accy += e0 * f0.y;
        }
        den = __shfl_sync(0xffffffffu, den, 0);
        float inv = (den > 0.f) ? 1.f / den : 0.f;
        float2 b = __ldg(&((const float2*)bias)[lane]);
        float ox = fmaxf(accx * inv + b.x, 0.f);
        float oy = fmaxf(accy * inv + b.y, 0.f);
        *(float2*)(g_agg + (size_t)node * 64 + lane * 2) = make_float2(ox, oy);
        atomicAdd(&sSum[lane * 2], ox);
        atomicAdd(&sSum[lane * 2 + 1], oy);
        atomicAdd(&sSq[lane * 2], ox * ox);
        atomicAdd(&sSq[lane * 2 + 1], oy * oy);
    }
    __syncthreads();
    if (tid < 64) {
        atomicAdd(&g_bn[tid], sSum[tid]);
        atomicAdd(&g_bn[64 + tid], sSq[tid]);
    }
}

// ---------------- mkbn: BN coeffs + zero bn (+optional pool zero) -----------
__global__ void mkbn_k(const float* __restrict__ gam, const float* __restrict__ bet,
                       int HC, int n, int zeroPool) {
    int c = threadIdx.x;  // 256 threads
    float s = 0.f, shv = 0.f;
    if (c < HC) {
        float inv_n = 1.f / (float)n;
        float mean = g_bn[c] * inv_n;
        float var = g_bn[HC + c] * inv_n - mean * mean;
        s = rsqrtf(var + BN_EPS) * gam[c];
        shv = bet[c] - mean * s;
    }
    __syncthreads();
    if (c < HC) { g_scl[c] = s; g_sh[c] = shv; }
    g_bn[c] = 0.f;
    g_bn[256 + c] = 0.f;
    if (zeroPool) {
        for (int i = c; i < NG * HIDC; i += 256) g_pool[i] = 0.f;
        if (c < NG) g_cnt[c] = 0.f;
    }
}

// ---------------- pool (sorted batch; final BN inline; counts fused) --------
#define POOL_BLKS 200
__global__ void pool2_k(const float* __restrict__ h, const int* __restrict__ batch) {
    int c = threadIdx.x & 63;
    int rl = threadIdx.x >> 6;
    int rowsPer = (NN + POOL_BLKS - 1) / POOL_BLKS;
    int r0 = blockIdx.x * rowsPer;
    int r1 = min(r0 + rowsPer, NN);
    float scl = g_scl[c], shv = g_sh[c];
    float acc = 0.f;
    float cntAcc = 0.f;
    int curg = -1;
    for (int r = r0 + rl; r < r1; r += 4) {
        int g = __ldg(&batch[r]);
        if (g != curg) {
            if (curg >= 0) {
                atomicAdd(&g_pool[curg * HIDC + c], acc);
                if (c == 0) atomicAdd(&g_cnt[curg], cntAcc);
            }
            curg = g;
            acc = 0.f;
            cntAcc = 0.f;
        }
        acc += h[(size_t)r * HIDC + c] * scl + shv;
        cntAcc += 1.f;
    }
    if (curg >= 0) {
        atomicAdd(&g_pool[curg * HIDC + c], acc);
        if (c == 0) atomicAdd(&g_cnt[curg], cntAcc);
    }
}
__global__ void fc_k(const float* __restrict__ fcW, const float* __restrict__ fcb,
                     float* __restrict__ out) {
    int idx = threadIdx.x;
    if (idx >= NG * NCLS) return;
    int g = idx / NCLS, c = idx - g * NCLS;
    float cnt = fmaxf(g_cnt[g], 1.0f);
    float inv = 1.0f / cnt;
    float s = fcb[c];
#pragma unroll
    for (int k = 0; k < HIDC; k++)
        s += (g_pool[g * HIDC + k] * inv) * fcW[k * NCLS + c];
    out[idx] = s;
}

// ---------------- host orchestration ----------------------------------------
extern "C" void kernel_launch(void* const* d_in, const int* in_sizes, int n_in,
                              void* d_out, int out_size) {
    const float* x   = (const float*)d_in[0];
    const int* ei    = (const int*)d_in[1];
    const int* batch = (const int*)d_in[2];
    const float* W1  = (const float*)d_in[3];
    const float* as1 = (const float*)d_in[4];
    const float* ad1 = (const float*)d_in[5];
    const float* b1  = (const float*)d_in[6];
    const float* g1  = (const float*)d_in[7];
    const float* be1 = (const float*)d_in[8];
    const float* W2  = (const float*)d_in[9];
    const float* as2 = (const float*)d_in[10];
    const float* ad2 = (const float*)d_in[11];
    const float* b2  = (const float*)d_in[12];
    const float* g2  = (const float*)d_in[13];
    const float* be2 = (const float*)d_in[14];
    const float* W3  = (const float*)d_in[15];
    const float* as3 = (const float*)d_in[16];
    const float* ad3 = (const float*)d_in[17];
    const float* b3  = (const float*)d_in[18];
    const float* g3  = (const float*)d_in[19];
    const float* be3 = (const float*)d_in[20];
    const float* fcW = (const float*)d_in[21];
    const float* fcb = (const float*)d_in[22];
    const int* src = ei;
    const int* dst = ei + EE;

    float *bnbuf, *aggbuf;
    int* curbuf;
    cudaGetSymbolAddress((void**)&aggbuf, g_agg);
    cudaGetSymbolAddress((void**)&bnbuf, g_bn);
    cudaGetSymbolAddress((void**)&curbuf, g_cur);

    // ---- build CSR (dst -> list of src) + initial bn zero ----
    zero_i_k<<<ceil_div(NN, 256), 256>>>(curbuf, NN);
    count_k<<<ceil_div(EE, 256), 256>>>(dst);
    scan_k<<<1, SCAN_T>>>();
    fill_k<<<ceil_div(EE, 256), 256>>>(src, dst);
    zero_f_k<<<2, 256>>>(bnbuf, 512);

    auto run_layer = [&](const float* in, int K, const float* W, const float* asv,
                         const float* adv, const float* b, const float* gam,
                         const float* bet, int H, int useBN, int zeroPool) {
        int HC = H * HIDC;
        dim3 gg(ceil_div(NN, BM), HC / BN);
        tgemm_k<<<gg, 256>>>(in, W, asv, adv, NN, K, HC, H, useBN);
        if (H == 4)
            agg4_k<<<ceil_div(NN * 32, 256), 256>>>(b);
        else
            agg1_k<<<ceil_div(NN * 32, 256), 256>>>(b);
        mkbn_k<<<1, 256>>>(gam, bet, HC, NN, zeroPool);
    };

    run_layer(x,      INC, W1, as1, ad1, b1, g1, be1, NHEADS, 0, 0);
    run_layer(aggbuf, 256, W2, as2, ad2, b2, g2, be2, NHEADS, 1, 0);
    run_layer(aggbuf, 256, W3, as3, ad3, b3, g3, be3, 1, 1, 1);

    // ---- global mean pool (applies layer-3 BN inline, counts fused) + FC ----
    pool2_k<<<POOL_BLKS, 256>>>(aggbuf, batch);
    fc_k<<<1, 640>>>(fcW, fcb, (float*)d_out);
}

// round 17
// speedup vs baseline: 1.3414x; 1.0439x over previous
#include <cuda_runtime.h>
#include <cuda_fp16.h>
#include <math.h>

#define NN 50000
#define EE 800000
#define INC 128
#define HIDC 64
#define NHEADS 4
#define NG 64
#define NCLS 10
#define BN_EPS 1e-5f

typedef unsigned int uint;

// ---------------- scratch (static device globals; zero at launch boundaries) -
__device__ __align__(16) __half g_hh[NN * 256];
__device__ __align__(16) float g_agg[NN * 256];
__device__ float g_as[NN * NHEADS];
__device__ float g_ad[NN * NHEADS];
__device__ int   g_rp[NN + 1];
__device__ int   g_cur[NN];      // zero at launch start (tail-zeroed by pool2_k)
__device__ int   g_col[EE];
__device__ float g_bn[2 * 256];  // zero at launch start (tail-zeroed by mkbn_k)
__device__ float g_scl[256];
__device__ float g_sh[256];
__device__ float g_pool[NG * HIDC];
__device__ float g_cnt[NG];

static inline int ceil_div(int a, int b) { return (a + b - 1) / b; }

// ---------------- CSR build (vectorized: 4 edges/thread) ---------------------
__global__ void count_k(const int* __restrict__ dst) {
    int t = blockIdx.x * blockDim.x + threadIdx.x;
    if (t * 4 >= EE) return;
    int4 d = __ldg((const int4*)&dst[t * 4]);
    atomicAdd(&g_cur[d.x], 1);
    atomicAdd(&g_cur[d.y], 1);
    atomicAdd(&g_cur[d.z], 1);
    atomicAdd(&g_cur[d.w], 1);
}

#define SCAN_T 512
__global__ void scan_k() {
    __shared__ int sh[SCAN_T];
    int t = threadIdx.x;
    int chunk = (NN + SCAN_T - 1) / SCAN_T;
    int base = t * chunk;
    int s = 0;
    for (int j = 0; j < chunk; j++) {
        int idx = base + j;
        if (idx < NN) s += g_cur[idx];
    }
    sh[t] = s;
    __syncthreads();
    for (int off = 1; off < SCAN_T; off <<= 1) {
        int v = (t >= off) ? sh[t - off] : 0;
        __syncthreads();
        sh[t] += v;
        __syncthreads();
    }
    int running = sh[t] - s;
    for (int j = 0; j < chunk; j++) {
        int idx = base + j;
        if (idx < NN) {
            int d = g_cur[idx];
            g_rp[idx] = running;
            g_cur[idx] = running;
            running += d;
        }
    }
    if (t == SCAN_T - 1) g_rp[NN] = sh[SCAN_T - 1];
}

__global__ void fill_k(const int* __restrict__ src, const int* __restrict__ dst) {
    int t = blockIdx.x * blockDim.x + threadIdx.x;
    if (t * 4 >= EE) return;
    int4 d = __ldg((const int4*)&dst[t * 4]);
    int4 s = __ldg((const int4*)&src[t * 4]);
    g_col[atomicAdd(&g_cur[d.x], 1)] = s.x;
    g_col[atomicAdd(&g_cur[d.y], 1)] = s.y;
    g_col[atomicAdd(&g_cur[d.z], 1)] = s.z;
    g_col[atomicAdd(&g_cur[d.w], 1)] = s.w;
}

// ---------------- fp16 2-term split GEMM with ldmatrix -----------------------
// a = ah + al (fp16, ~22-bit coverage); b = fp16(b).
// C = ah*bh + al*bh;  error ~ a*(b - bh) ~ 2.4e-4 relative (R10 precedent).
#define BM 128
#define BN 64
#define BK 32
#define SA_H 40        // A row stride in halves (80B): ldmatrix conflict-free
#define SB_U 36        // B row stride in uints (144B): ldmatrix conflict-free

__device__ __forceinline__ uint pack2h(__half x, __half y) {
    __half2 t = __halves2half2(x, y);
    return *(uint*)&t;
}
__device__ __forceinline__ void mma16(float* c, const uint* a, const uint* b) {
    asm volatile(
        "mma.sync.aligned.m16n8k16.row.col.f32.f16.f16.f32 "
        "{%0,%1,%2,%3}, {%4,%5,%6,%7}, {%8,%9}, {%0,%1,%2,%3};"
        : "+f"(c[0]), "+f"(c[1]), "+f"(c[2]), "+f"(c[3])
        : "r"(a[0]), "r"(a[1]), "r"(a[2]), "r"(a[3]), "r"(b[0]), "r"(b[1]));
}
__device__ __forceinline__ void ldsm4(uint& r0, uint& r1, uint& r2, uint& r3, uint addr) {
    asm volatile("ldmatrix.sync.aligned.m8n8.x4.shared.b16 {%0,%1,%2,%3}, [%4];"
                 : "=r"(r0), "=r"(r1), "=r"(r2), "=r"(r3) : "r"(addr));
}
__device__ __forceinline__ void ldsm4t(uint& r0, uint& r1, uint& r2, uint& r3, uint addr) {
    asm volatile("ldmatrix.sync.aligned.m8n8.x4.trans.shared.b16 {%0,%1,%2,%3}, [%4];"
                 : "=r"(r0), "=r"(r1), "=r"(r2), "=r"(r3) : "r"(addr));
}

__global__ void __launch_bounds__(256) tgemm_k(const float* __restrict__ A,
                                               const float* __restrict__ B,
                                               const float* __restrict__ asrc,
                                               const float* __restrict__ adst,
                                               int n, int K, int M, int H,
                                               int useBN) {
    __shared__ __align__(16) __half sAh[BM][SA_H];
    __shared__ __align__(16) __half sAl[BM][SA_H];
    __shared__ __align__(16) uint sB[BK][SB_U];
    __shared__ float sAs[BM];
    __shared__ float sAd[BM];
    int tid = threadIdx.x;
    int lane = tid & 31;
    int wid = tid >> 5;
    int warpM = wid >> 1, warpN = wid & 1;
    int gid = lane >> 2, tq = lane & 3;
    int row0 = blockIdx.x * BM, col0 = blockIdx.y * BN;
    int hd = blockIdx.y;

    int a_r = tid >> 3, a_q4 = (tid & 7) * 4;
    int b_n2 = tid & 31, b_k = tid >> 5;

    float4 pa[4];
    float2 pbv[4];

    auto loadTiles = [&](int k0) {
        float scl0 = 1.f, scl1 = 1.f, scl2 = 1.f, scl3 = 1.f;
        float sh0 = 0.f, sh1 = 0.f, sh2 = 0.f, sh3 = 0.f;
        if (useBN) {
            scl0 = g_scl[k0 + a_q4 + 0]; sh0 = g_sh[k0 + a_q4 + 0];
            scl1 = g_scl[k0 + a_q4 + 1]; sh1 = g_sh[k0 + a_q4 + 1];
            scl2 = g_scl[k0 + a_q4 + 2]; sh2 = g_sh[k0 + a_q4 + 2];
            scl3 = g_scl[k0 + a_q4 + 3]; sh3 = g_sh[k0 + a_q4 + 3];
        }
#pragma unroll
        for (int i = 0; i < 4; i++) {
            int gr = row0 + i * 32 + a_r;
            float4 v = make_float4(0.f, 0.f, 0.f, 0.f);
            if (gr < n) v = *(const float4*)&A[(size_t)gr * K + k0 + a_q4];
            if (useBN) {
                v.x = v.x * scl0 + sh0;
                v.y = v.y * scl1 + sh1;
                v.z = v.z * scl2 + sh2;
                v.w = v.w * scl3 + sh3;
            }
            pa[i] = v;
        }
#pragma unroll
        for (int i = 0; i < 4; i++) {
            int k = b_k + i * 8;
            pbv[i] = *(const float2*)&B[(size_t)(k0 + k) * M + col0 + 2 * b_n2];
        }
    };
    auto storeTiles = [&]() {
#pragma unroll
        for (int i = 0; i < 4; i++) {
            int r = i * 32 + a_r;
            float vv[4] = {pa[i].x, pa[i].y, pa[i].z, pa[i].w};
            __half hh[4], hl[4];
#pragma unroll
            for (int j = 0; j < 4; j++) {
                hh[j] = __float2half_rn(vv[j]);
                hl[j] = __float2half_rn(vv[j] - __half2float(hh[j]));
            }
            *(uint2*)&sAh[r][a_q4] = make_uint2(pack2h(hh[0], hh[1]), pack2h(hh[2], hh[3]));
            *(uint2*)&sAl[r][a_q4] = make_uint2(pack2h(hl[0], hl[1]), pack2h(hl[2], hl[3]));
        }
#pragma unroll
        for (int i = 0; i < 4; i++) {
            int k = b_k + i * 8;
            sB[k][b_n2] = pack2h(__float2half_rn(pbv[i].x), __float2half_rn(pbv[i].y));
        }
    };

    float c[2][4][4];
#pragma unroll
    for (int mt = 0; mt < 2; mt++)
#pragma unroll
        for (int nt = 0; nt < 4; nt++)
#pragma unroll
            for (int j = 0; j < 4; j++) c[mt][nt][j] = 0.f;

    uint baseAh = (uint)__cvta_generic_to_shared(&sAh[0][0]);
    uint baseAl = (uint)__cvta_generic_to_shared(&sAl[0][0]);
    uint baseB = (uint)__cvta_generic_to_shared(&sB[0][0]);
    int r8 = lane & 7, q = lane >> 3;
    int aRowOff = ((q & 1) << 3) + r8;
    int aColOff = (q >> 1) << 3;
    int bUcol = warpN * 16 + q * 4;

    int nk = K / BK;
    loadTiles(0);
    for (int it = 0; it < nk; it++) {
        storeTiles();
        __syncthreads();
        if (it + 1 < nk) loadTiles((it + 1) * BK);
#pragma unroll
        for (int ks = 0; ks < 2; ks++) {
            uint ah[2][4], al[2][4], bh[4][2];
#pragma unroll
            for (int mt = 0; mt < 2; mt++) {
                int m = warpM * 32 + mt * 16 + aRowOff;
                uint aoff = (uint)(m * (SA_H * 2) + (ks * 16 + aColOff) * 2);
                ldsm4(ah[mt][0], ah[mt][1], ah[mt][2], ah[mt][3], baseAh + aoff);
                ldsm4(al[mt][0], al[mt][1], al[mt][2], al[mt][3], baseAl + aoff);
            }
            {
                uint off0 = (uint)(((ks * 16 + r8) * SB_U + bUcol) * 4);
                uint off1 = (uint)(((ks * 16 + 8 + r8) * SB_U + bUcol) * 4);
                ldsm4t(bh[0][0], bh[1][0], bh[2][0], bh[3][0], baseB + off0);
                ldsm4t(bh[0][1], bh[1][1], bh[2][1], bh[3][1], baseB + off1);
            }
#pragma unroll
            for (int mt = 0; mt < 2; mt++)
#pragma unroll
                for (int nt = 0; nt < 4; nt++) {
                    mma16(c[mt][nt], ah[mt], bh[nt]);
                    mma16(c[mt][nt], al[mt], bh[nt]);
                }
        }
        __syncthreads();
    }

    // ---- epilogue: fp16 h store + fused attention logits ----
    if (tid < BM) { sAs[tid] = 0.f; sAd[tid] = 0.f; }
    __syncthreads();

    float pAs[4] = {0.f, 0.f, 0.f, 0.f};
    float pAd[4] = {0.f, 0.f, 0.f, 0.f};
#pragma unroll
    for (int nt = 0; nt < 4; nt++) {
        int cc = warpN * 32 + nt * 8 + tq * 2;
        float a0 = __ldg(&asrc[hd * HIDC + cc]);
        float a1 = __ldg(&asrc[hd * HIDC + cc + 1]);
        float d0 = __ldg(&adst[hd * HIDC + cc]);
        float d1 = __ldg(&adst[hd * HIDC + cc + 1]);
#pragma unroll
        for (int mt = 0; mt < 2; mt++) {
            pAs[mt * 2 + 0] += c[mt][nt][0] * a0 + c[mt][nt][1] * a1;
            pAs[mt * 2 + 1] += c[mt][nt][2] * a0 + c[mt][nt][3] * a1;
            pAd[mt * 2 + 0] += c[mt][nt][0] * d0 + c[mt][nt][1] * d1;
            pAd[mt * 2 + 1] += c[mt][nt][2] * d0 + c[mt][nt][3] * d1;
        }
#pragma unroll
        for (int mt = 0; mt < 2; mt++) {
            int r0g = row0 + warpM * 32 + mt * 16 + gid;
            int r1g = r0g + 8;
            int gc = col0 + cc;
            if (r0g < n)
                *(half2*)&g_hh[(size_t)r0g * M + gc] =
                    __floats2half2_rn(c[mt][nt][0], c[mt][nt][1]);
            if (r1g < n)
                *(half2*)&g_hh[(size_t)r1g * M + gc] =
                    __floats2half2_rn(c[mt][nt][2], c[mt][nt][3]);
        }
    }
#pragma unroll
    for (int j = 0; j < 4; j++) {
        pAs[j] += __shfl_xor_sync(0xffffffffu, pAs[j], 1);
        pAs[j] += __shfl_xor_sync(0xffffffffu, pAs[j], 2);
        pAd[j] += __shfl_xor_sync(0xffffffffu, pAd[j], 1);
        pAd[j] += __shfl_xor_sync(0xffffffffu, pAd[j], 2);
    }
    if (tq == 0) {
#pragma unroll
        for (int mt = 0; mt < 2; mt++)
#pragma unroll
            for (int p = 0; p < 2; p++) {
                int lr = warpM * 32 + mt * 16 + p * 8 + gid;
                atomicAdd(&sAs[lr], pAs[mt * 2 + p]);
                atomicAdd(&sAd[lr], pAd[mt * 2 + p]);
            }
    }
    __syncthreads();
    if (tid < BM) {
        int r = row0 + tid;
        if (r < n) {
            g_as[r * H + hd] = sAs[tid];
            g_ad[r * H + hd] = sAd[tid];
        }
    }
}

// ---------------- gather aggregation, H=4 + fused BN stats ------------------
__global__ void agg4_k(const float* __restrict__ bias) {
    __shared__ float sSum[256];
    __shared__ float sSq[256];
    int tid = threadIdx.x;
    int warp = (blockIdx.x * blockDim.x + tid) >> 5;
    int lane = tid & 31;
    sSum[tid] = 0.f;
    sSq[tid] = 0.f;
    __syncthreads();
    if (warp < NN) {
        int node = warp;
        int hs = lane >> 3;
        float ad_h = (lane < 4) ? g_ad[node * 4 + lane] : 0.f;
        float den = 0.f;
        float acc[8] = {0.f, 0.f, 0.f, 0.f, 0.f, 0.f, 0.f, 0.f};
        int beg = g_rp[node], end = g_rp[node + 1];
        int j = beg;
        for (; j + 3 < end; j += 4) {
            int s0 = __ldg(&g_col[j]);
            int s1 = __ldg(&g_col[j + 1]);
            int s2 = __ldg(&g_col[j + 2]);
            int s3 = __ldg(&g_col[j + 3]);
            float e0 = 0.f, e1 = 0.f, e2 = 0.f, e3 = 0.f;
            if (lane < 4) {
                float v0 = __ldg(&g_as[s0 * 4 + lane]) + ad_h;
                float v1 = __ldg(&g_as[s1 * 4 + lane]) + ad_h;
                float v2 = __ldg(&g_as[s2 * 4 + lane]) + ad_h;
                float v3 = __ldg(&g_as[s3 * 4 + lane]) + ad_h;
                v0 = (v0 > 0.f) ? v0 : 0.2f * v0;
                v1 = (v1 > 0.f) ? v1 : 0.2f * v1;
                v2 = (v2 > 0.f) ? v2 : 0.2f * v2;
                v3 = (v3 > 0.f) ? v3 : 0.2f * v3;
                e0 = __expf(v0); e1 = __expf(v1);
                e2 = __expf(v2); e3 = __expf(v3);
                den += (e0 + e1) + (e2 + e3);
            }
            uint4 u0 = __ldg((const uint4*)&g_hh[(size_t)s0 * 256 + lane * 8]);
            uint4 u1 = __ldg((const uint4*)&g_hh[(size_t)s1 * 256 + lane * 8]);
            uint4 u2 = __ldg((const uint4*)&g_hh[(size_t)s2 * 256 + lane * 8]);
            uint4 u3 = __ldg((const uint4*)&g_hh[(size_t)s3 * 256 + lane * 8]);
            float ex0 = __shfl_sync(0xffffffffu, e0, hs);
            float ex1 = __shfl_sync(0xffffffffu, e1, hs);
            float ex2 = __shfl_sync(0xffffffffu, e2, hs);
            float ex3 = __shfl_sync(0xffffffffu, e3, hs);
            float2 f;
            f = __half22float2(*(half2*)&u0.x); acc[0] += ex0 * f.x; acc[1] += ex0 * f.y;
            f = __half22float2(*(half2*)&u0.y); acc[2] += ex0 * f.x; acc[3] += ex0 * f.y;
            f = __half22float2(*(half2*)&u0.z); acc[4] += ex0 * f.x; acc[5] += ex0 * f.y;
            f = __half22float2(*(half2*)&u0.w); acc[6] += ex0 * f.x; acc[7] += ex0 * f.y;
            f = __half22float2(*(half2*)&u1.x); acc[0] += ex1 * f.x; acc[1] += ex1 * f.y;
            f = __half22float2(*(half2*)&u1.y); acc[2] += ex1 * f.x; acc[3] += ex1 * f.y;
            f = __half22float2(*(half2*)&u1.z); acc[4] += ex1 * f.x; acc[5] += ex1 * f.y;
            f = __half22float2(*(half2*)&u1.w); acc[6] += ex1 * f.x; acc[7] += ex1 * f.y;
            f = __half22float2(*(half2*)&u2.x); acc[0] += ex2 * f.x; acc[1] += ex2 * f.y;
            f = __half22float2(*(half2*)&u2.y); acc[2] += ex2 * f.x; acc[3] += ex2 * f.y;
            f = __half22float2(*(half2*)&u2.z); acc[4] += ex2 * f.x; acc[5] += ex2 * f.y;
            f = __half22float2(*(half2*)&u2.w); acc[6] += ex2 * f.x; acc[7] += ex2 * f.y;
            f = __half22float2(*(half2*)&u3.x); acc[0] += ex3 * f.x; acc[1] += ex3 * f.y;
            f = __half22float2(*(half2*)&u3.y); acc[2] += ex3 * f.x; acc[3] += ex3 * f.y;
            f = __half22float2(*(half2*)&u3.z); acc[4] += ex3 * f.x; acc[5] += ex3 * f.y;
            f = __half22float2(*(half2*)&u3.w); acc[6] += ex3 * f.x; acc[7] += ex3 * f.y;
        }
        for (; j < end; j++) {
            int s0 = __ldg(&g_col[j]);
            float e0 = 0.f;
            if (lane < 4) {
                float v0 = __ldg(&g_as[s0 * 4 + lane]) + ad_h;
                v0 = (v0 > 0.f) ? v0 : 0.2f * v0;
                e0 = __expf(v0);
                den += e0;
            }
            uint4 u0 = __ldg((const uint4*)&g_hh[(size_t)s0 * 256 + lane * 8]);
            float ex0 = __shfl_sync(0xffffffffu, e0, hs);
            float2 f;
            f = __half22float2(*(half2*)&u0.x); acc[0] += ex0 * f.x; acc[1] += ex0 * f.y;
            f = __half22float2(*(half2*)&u0.y); acc[2] += ex0 * f.x; acc[3] += ex0 * f.y;
            f = __half22float2(*(half2*)&u0.z); acc[4] += ex0 * f.x; acc[5] += ex0 * f.y;
            f = __half22float2(*(half2*)&u0.w); acc[6] += ex0 * f.x; acc[7] += ex0 * f.y;
        }
        float denh = __shfl_sync(0xffffffffu, den, hs);
        float inv = (denh > 0.f) ? 1.f / denh : 0.f;
        float4 b0 = __ldg(&((const float4*)bias)[lane * 2]);
        float4 b1 = __ldg(&((const float4*)bias)[lane * 2 + 1]);
        float o[8];
        o[0] = fmaxf(acc[0] * inv + b0.x, 0.f);
        o[1] = fmaxf(acc[1] * inv + b0.y, 0.f);
        o[2] = fmaxf(acc[2] * inv + b0.z, 0.f);
        o[3] = fmaxf(acc[3] * inv + b0.w, 0.f);
        o[4] = fmaxf(acc[4] * inv + b1.x, 0.f);
        o[5] = fmaxf(acc[5] * inv + b1.y, 0.f);
        o[6] = fmaxf(acc[6] * inv + b1.z, 0.f);
        o[7] = fmaxf(acc[7] * inv + b1.w, 0.f);
        float* op = g_agg + (size_t)node * 256 + lane * 8;
        *(float4*)op = make_float4(o[0], o[1], o[2], o[3]);
        *(float4*)(op + 4) = make_float4(o[4], o[5], o[6], o[7]);
#pragma unroll
        for (int q = 0; q < 8; q++) {
            atomicAdd(&sSum[lane * 8 + q], o[q]);
            atomicAdd(&sSq[lane * 8 + q], o[q] * o[q]);
        }
    }
    __syncthreads();
    atomicAdd(&g_bn[tid], sSum[tid]);
    atomicAdd(&g_bn[256 + tid], sSq[tid]);
}

// ---------------- gather aggregation, H=1 + fused BN stats ------------------
__global__ void agg1_k(const float* __restrict__ bias) {
    __shared__ float sSum[64];
    __shared__ float sSq[64];
    int tid = threadIdx.x;
    int warp = (blockIdx.x * blockDim.x + tid) >> 5;
    int lane = tid & 31;
    if (tid < 64) { sSum[tid] = 0.f; sSq[tid] = 0.f; }
    __syncthreads();
    if (warp < NN) {
        int node = warp;
        float ad0 = g_ad[node];
        float den = 0.f;
        float accx = 0.f, accy = 0.f;
        int beg = g_rp[node], end = g_rp[node + 1];
        int j = beg;
        for (; j + 3 < end; j += 4) {
            int s0 = __ldg(&g_col[j]);
            int s1 = __ldg(&g_col[j + 1]);
            int s2 = __ldg(&g_col[j + 2]);
            int s3 = __ldg(&g_col[j + 3]);
            float e0 = 0.f, e1 = 0.f, e2 = 0.f, e3 = 0.f;
            if (lane == 0) {
                float v0 = __ldg(&g_as[s0]) + ad0;
                float v1 = __ldg(&g_as[s1]) + ad0;
                float v2 = __ldg(&g_as[s2]) + ad0;
                float v3 = __ldg(&g_as[s3]) + ad0;
                v0 = (v0 > 0.f) ? v0 : 0.2f * v0;
                v1 = (v1 > 0.f) ? v1 : 0.2f * v1;
                v2 = (v2 > 0.f) ? v2 : 0.2f * v2;
                v3 = (v3 > 0.f) ? v3 : 0.2f * v3;
                e0 = __expf(v0); e1 = __expf(v1);
                e2 = __expf(v2); e3 = __expf(v3);
                den += (e0 + e1) + (e2 + e3);
            }
            uint u0 = __ldg((const uint*)&g_hh[(size_t)s0 * 64 + lane * 2]);
            uint u1 = __ldg((const uint*)&g_hh[(size_t)s1 * 64 + lane * 2]);
            uint u2 = __ldg((const uint*)&g_hh[(size_t)s2 * 64 + lane * 2]);
            uint u3 = __ldg((const uint*)&g_hh[(size_t)s3 * 64 + lane * 2]);
            e0 = __shfl_sync(0xffffffffu, e0, 0);
            e1 = __shfl_sync(0xffffffffu, e1, 0);
            e2 = __shfl_sync(0xffffffffu, e2, 0);
            e3 = __shfl_sync(0xffffffffu, e3, 0);
            float2 f0 = __half22float2(*(half2*)&u0);
            float2 f1 = __half22float2(*(half2*)&u1);
            float2 f2 = __half22float2(*(half2*)&u2);
            float2 f3 = __half22float2(*(half2*)&u3);
            accx += (e0 * f0.x + e1 * f1.x) + (e2 * f2.x + e3 * f3.x);
            accy += (e0 * f0.y + e1 * f1.y) + (e2 * f2.y + e3 * f3.y);
        }
        for (; j < end; j++) {
            int s0 = __ldg(&g_col[j]);
            float e0 = 0.f;
            if (lane == 0) {
                float v0 = __ldg(&g_as[s0]) + ad0;
                v0 = (v0 > 0.f) ? v0 : 0.2f * v0;
                e0 = __expf(v0);
                den += e0;
            }
            uint u0 = __ldg((const uint*)&g_hh[(size_t)s0 * 64 + lane * 2]);
            e0 = __shfl_sync(0xffffffffu, e0, 0);
            float2 f0 = __half22float2(*(half2*)&u0);
            accx += e0 * f0.x;
            accy += e0 * f0.y;
        }
        den = __shfl_sync(0xffffffffu, den, 0);
        float inv = (den > 0.f) ? 1.f / den : 0.f;
        float2 b = __ldg(&((const float2*)bias)[lane]);
        float ox = fmaxf(accx * inv + b.x, 0.f);
        float oy = fmaxf(accy * inv + b.y, 0.f);
        *(float2*)(g_agg + (size_t)node * 64 + lane * 2) = make_float2(ox, oy);
        atomicAdd(&sSum[lane * 2], ox);
        atomicAdd(&sSum[lane * 2 + 1], oy);
        atomicAdd(&sSq[lane * 2], ox * ox);
        atomicAdd(&sSq[lane * 2 + 1], oy * oy);
    }
    __syncthreads();
    if (tid < 64) {
        atomicAdd(&g_bn[tid], sSum[tid]);
        atomicAdd(&g_bn[64 + tid], sSq[tid]);
    }
}

// ---------------- mkbn: BN coeffs + zero bn (+optional pool zero) -----------
__global__ void mkbn_k(const float* __restrict__ gam, const float* __restrict__ bet,
                       int HC, int n, int zeroPool) {
    int c = threadIdx.x;  // 256 threads
    float s = 0.f, shv = 0.f;
    if (c < HC) {
        float inv_n = 1.f / (float)n;
        float mean = g_bn[c] * inv_n;
        float var = g_bn[HC + c] * inv_n - mean * mean;
        s = rsqrtf(var + BN_EPS) * gam[c];
        shv = bet[c] - mean * s;
    }
    __syncthreads();
    if (c < HC) { g_scl[c] = s; g_sh[c] = shv; }
    g_bn[c] = 0.f;
    g_bn[256 + c] = 0.f;
    if (zeroPool) {
        for (int i = c; i < NG * HIDC; i += 256) g_pool[i] = 0.f;
        if (c < NG) g_cnt[c] = 0.f;
    }
}

// ---------------- pool (sorted batch; final BN inline; counts + cur-zero) ---
#define POOL_BLKS 200
__global__ void pool2_k(const float* __restrict__ h, const int* __restrict__ batch) {
    int c = threadIdx.x & 63;
    int rl = threadIdx.x >> 6;
    int rowsPer = (NN + POOL_BLKS - 1) / POOL_BLKS;
    int r0 = blockIdx.x * rowsPer;
    int r1 = min(r0 + rowsPer, NN);
    float scl = g_scl[c], shv = g_sh[c];
    float acc = 0.f;
    float cntAcc = 0.f;
    int curg = -1;
    for (int r = r0 + rl; r < r1; r += 4) {
        int g = __ldg(&batch[r]);
        if (g != curg) {
            if (curg >= 0) {
                atomicAdd(&g_pool[curg * HIDC + c], acc);
                if (c == 0) atomicAdd(&g_cnt[curg], cntAcc);
            }
            curg = g;
            acc = 0.f;
            cntAcc = 0.f;
        }
        acc += h[(size_t)r * HIDC + c] * scl + shv;
        cntAcc += 1.f;
    }
    if (curg >= 0) {
        atomicAdd(&g_pool[curg * HIDC + c], acc);
        if (c == 0) atomicAdd(&g_cnt[curg], cntAcc);
    }
    // tail: re-zero g_cur for the next graph replay (valid: state invariant
    // across launches — globals start zero, every launch ends with them zero)
    int gi = blockIdx.x * blockDim.x + threadIdx.x;
    if (gi < NN) g_cur[gi] = 0;
}
__global__ void fc_k(const float* __restrict__ fcW, const float* __restrict__ fcb,
                     float* __restrict__ out) {
    int idx = threadIdx.x;
    if (idx >= NG * NCLS) return;
    int g = idx / NCLS, c = idx - g * NCLS;
    float cnt = fmaxf(g_cnt[g], 1.0f);
    float inv = 1.0f / cnt;
    float s = fcb[c];
#pragma unroll
    for (int k = 0; k < HIDC; k++)
        s += (g_pool[g * HIDC + k] * inv) * fcW[k * NCLS + c];
    out[idx] = s;
}

// ---------------- host orchestration ----------------------------------------
extern "C" void kernel_launch(void* const* d_in, const int* in_sizes, int n_in,
                              void* d_out, int out_size) {
    const float* x   = (const float*)d_in[0];
    const int* ei    = (const int*)d_in[1];
    const int* batch = (const int*)d_in[2];
    const float* W1  = (const float*)d_in[3];
    const float* as1 = (const float*)d_in[4];
    const float* ad1 = (const float*)d_in[5];
    const float* b1  = (const float*)d_in[6];
    const float* g1  = (const float*)d_in[7];
    const float* be1 = (const float*)d_in[8];
    const float* W2  = (const float*)d_in[9];
    const float* as2 = (const float*)d_in[10];
    const float* ad2 = (const float*)d_in[11];
    const float* b2  = (const float*)d_in[12];
    const float* g2  = (const float*)d_in[13];
    const float* be2 = (const float*)d_in[14];
    const float* W3  = (const float*)d_in[15];
    const float* as3 = (const float*)d_in[16];
    const float* ad3 = (const float*)d_in[17];
    const float* b3  = (const float*)d_in[18];
    const float* g3  = (const float*)d_in[19];
    const float* be3 = (const float*)d_in[20];
    const float* fcW = (const float*)d_in[21];
    const float* fcb = (const float*)d_in[22];
    const int* src = ei;
    const int* dst = ei + EE;

    float* aggbuf;
    cudaGetSymbolAddress((void**)&aggbuf, g_agg);

    // ---- build CSR (dst -> list of src); g_cur is zero at launch start ----
    count_k<<<ceil_div(EE / 4, 256), 256>>>(dst);
    scan_k<<<1, SCAN_T>>>();
    fill_k<<<ceil_div(EE / 4, 256), 256>>>(src, dst);

    auto run_layer = [&](const float* in, int K, const float* W, const float* asv,
                         const float* adv, const float* b, const float* gam,
                         const float* bet, int H, int useBN, int zeroPool) {
        int HC = H * HIDC;
        dim3 gg(ceil_div(NN, BM), HC / BN);
        tgemm_k<<<gg, 256>>>(in, W, asv, adv, NN, K, HC, H, useBN);
        if (H == 4)
            agg4_k<<<ceil_div(NN * 32, 256), 256>>>(b);
        else
            agg1_k<<<ceil_div(NN * 32, 256), 256>>>(b);
        mkbn_k<<<1, 256>>>(gam, bet, HC, NN, zeroPool);
    };

    run_layer(x,      INC, W1, as1, ad1, b1, g1, be1, NHEADS, 0, 0);
    run_layer(aggbuf, 256, W2, as2, ad2, b2, g2, be2, NHEADS, 1, 0);
    run_layer(aggbuf, 256, W3, as3, ad3, b3, g3, be3, 1, 1, 1);

    // ---- global mean pool (layer-3 BN inline, counts fused, cur re-zero) ----
    pool2_k<<<POOL_BLKS, 256>>>(aggbuf, batch);
    fc_k<<<1, 640>>>(fcW, fcb, (float*)d_out);
}